// round 1
// baseline (speedup 1.0000x reference)
#include <cuda_runtime.h>
#include <math.h>

// Problem dims
#define BSZ   2
#define QLEN  2048
#define DIM   1024
#define NH    16
#define HD    64
#define MTOT  (BSZ*QLEN)   // 4096

// Scratch (device globals: allocation-free)
__device__ float g_Q[BSZ*NH*QLEN*HD];
__device__ float g_K[BSZ*NH*QLEN*HD];
__device__ float g_V[BSZ*NH*QLEN*HD];
__device__ float g_C[MTOT*DIM];

// ---------------------------------------------------------------------------
// GEMM: out = (A[M,K] @ W[K,N] + bias[N]) * scale
// M=4096, N=1024, K=1024. 128x128 block tile, BK=8, 256 threads, 8x8/thread.
// MODE 0: row-major out[m*N+n]
// MODE 1: head-split out[((b*NH+h)*QLEN+q)*HD+d] with b=m>>11,q=m&2047,h=n>>6,d=n&63
// ---------------------------------------------------------------------------
template<int MODE>
__global__ void __launch_bounds__(256) sgemm_bias(
    const float* __restrict__ A, const float* __restrict__ W,
    const float* __restrict__ bias, float* __restrict__ out, float scale)
{
    __shared__ float As[8][128];
    __shared__ float Bs[8][128];

    const int tid = threadIdx.x;
    const int br  = blockIdx.y * 128;
    const int bc  = blockIdx.x * 128;

    const int aRow = tid >> 1;          // 0..127
    const int aK   = (tid & 1) * 4;     // 0 or 4
    const int bK   = tid >> 5;          // 0..7
    const int bCol = (tid & 31) * 4;    // 0..124

    const int r0 = (tid >> 4) * 8;      // 0..120
    const int c0 = (tid & 15) * 8;      // 0..120

    float acc[8][8];
    #pragma unroll
    for (int i = 0; i < 8; i++)
        #pragma unroll
        for (int j = 0; j < 8; j++) acc[i][j] = 0.0f;

    for (int k0 = 0; k0 < DIM; k0 += 8) {
        float4 av = *(const float4*)(&A[(size_t)(br + aRow) * DIM + k0 + aK]);
        As[aK + 0][aRow] = av.x;
        As[aK + 1][aRow] = av.y;
        As[aK + 2][aRow] = av.z;
        As[aK + 3][aRow] = av.w;
        float4 bv = *(const float4*)(&W[(size_t)(k0 + bK) * DIM + bc + bCol]);
        *(float4*)(&Bs[bK][bCol]) = bv;
        __syncthreads();

        #pragma unroll
        for (int k = 0; k < 8; k++) {
            float a[8], b[8];
            #pragma unroll
            for (int i = 0; i < 8; i++) a[i] = As[k][r0 + i];
            #pragma unroll
            for (int j = 0; j < 8; j++) b[j] = Bs[k][c0 + j];
            #pragma unroll
            for (int i = 0; i < 8; i++)
                #pragma unroll
                for (int j = 0; j < 8; j++) acc[i][j] += a[i] * b[j];
        }
        __syncthreads();
    }

    #pragma unroll
    for (int i = 0; i < 8; i++) {
        #pragma unroll
        for (int j = 0; j < 8; j++) {
            const int m = br + r0 + i;
            const int n = bc + c0 + j;
            float v = (acc[i][j] + bias[n]) * scale;
            if (MODE == 0) {
                out[(size_t)m * DIM + n] = v;
            } else {
                const int b = m >> 11, q = m & 2047, h = n >> 6, d = n & 63;
                out[(((size_t)b * NH + h) * QLEN + q) * HD + d] = v;
            }
        }
    }
}

// ---------------------------------------------------------------------------
// Flash attention (fp32). One block per (batch*head, 64-query tile).
// 256 threads as 16x16: thread (ty,tx) owns S/O micro-tile [ty*4..+3][tx*4..+3].
// Streams 64-key tiles of K and V through smem; online softmax.
// ---------------------------------------------------------------------------
#define PAD 65
#define SMEM_ATTN_BYTES ((4*64*PAD + 4*64) * 4)

__global__ void __launch_bounds__(256) attn_kernel(
    const float* __restrict__ Q, const float* __restrict__ K,
    const float* __restrict__ V, const float* __restrict__ mask,
    float* __restrict__ ctx)
{
    extern __shared__ float sm[];
    float* Qs   = sm;                 // 64 x PAD
    float* Ks   = Qs  + 64 * PAD;     // 64 x PAD
    float* Vs   = Ks  + 64 * PAD;     // 64 x PAD
    float* Ssh  = Vs  + 64 * PAD;     // 64 x PAD
    float* msh  = Ssh + 64 * PAD;     // 64
    float* lsh  = msh + 64;           // 64
    float* alsh = lsh + 64;           // 64
    float* madd = alsh + 64;          // 64

    const int tid = threadIdx.x;
    const int bh  = blockIdx.x;               // 0..31
    const int b   = bh >> 4;
    const int h   = bh & 15;
    const int q0  = blockIdx.y * 64;

    const float* Qh = Q + (size_t)bh * QLEN * HD;
    const float* Kh = K + (size_t)bh * QLEN * HD;
    const float* Vh = V + (size_t)bh * QLEN * HD;
    const float* mb = mask + (size_t)b * QLEN;

    const int ty  = tid >> 4;
    const int tx  = tid & 15;
    const int ty4 = ty * 4;
    const int tx4 = tx * 4;

    // softmax role: thread group of 4 per row
    const int srow = tid >> 2;
    const int sg   = tid & 3;

    // Load Q tile
    #pragma unroll
    for (int it = 0; it < 16; it++) {
        int idx = tid + it * 256;             // 0..4095
        int r = idx >> 6, c = idx & 63;
        Qs[r * PAD + c] = Qh[(size_t)(q0 + r) * HD + c];
    }
    if (tid < 64) { msh[tid] = -1e30f; lsh[tid] = 0.0f; }

    float o[4][4];
    #pragma unroll
    for (int i = 0; i < 4; i++)
        #pragma unroll
        for (int j = 0; j < 4; j++) o[i][j] = 0.0f;

    for (int t = 0; t < QLEN / 64; t++) {
        const int kk0 = t * 64;
        __syncthreads();   // prev PV done before overwriting Ks/Vs/madd

        #pragma unroll
        for (int it = 0; it < 16; it++) {
            int idx = tid + it * 256;
            int r = idx >> 6, c = idx & 63;
            Ks[r * PAD + c] = Kh[(size_t)(kk0 + r) * HD + c];
            Vs[r * PAD + c] = Vh[(size_t)(kk0 + r) * HD + c];
        }
        if (tid < 64) madd[tid] = -1e30f * (1.0f - mb[kk0 + tid]);
        __syncthreads();

        // S = Q @ K^T  (Q pre-scaled by 1/sqrt(HD))
        float s[4][4];
        #pragma unroll
        for (int i = 0; i < 4; i++)
            #pragma unroll
            for (int j = 0; j < 4; j++) s[i][j] = 0.0f;

        #pragma unroll 4
        for (int kk = 0; kk < 64; kk++) {
            float a[4], bb[4];
            #pragma unroll
            for (int i = 0; i < 4; i++) a[i]  = Qs[(ty4 + i) * PAD + kk];
            #pragma unroll
            for (int j = 0; j < 4; j++) bb[j] = Ks[(tx4 + j) * PAD + kk];
            #pragma unroll
            for (int i = 0; i < 4; i++)
                #pragma unroll
                for (int j = 0; j < 4; j++) s[i][j] += a[i] * bb[j];
        }
        #pragma unroll
        for (int i = 0; i < 4; i++)
            #pragma unroll
            for (int j = 0; j < 4; j++)
                Ssh[(ty4 + i) * PAD + tx4 + j] = s[i][j] + madd[tx4 + j];
        __syncthreads();

        // online softmax: 4 threads per row
        {
            float tmax = -1e30f;
            for (int c = sg; c < 64; c += 4)
                tmax = fmaxf(tmax, Ssh[srow * PAD + c]);
            tmax = fmaxf(tmax, __shfl_xor_sync(0xffffffffu, tmax, 1));
            tmax = fmaxf(tmax, __shfl_xor_sync(0xffffffffu, tmax, 2));

            const float m_old = msh[srow];
            const float m_new = fmaxf(m_old, tmax);
            float sum = 0.0f;
            for (int c = sg; c < 64; c += 4) {
                float p = __expf(Ssh[srow * PAD + c] - m_new);
                Ssh[srow * PAD + c] = p;
                sum += p;
            }
            sum += __shfl_xor_sync(0xffffffffu, sum, 1);
            sum += __shfl_xor_sync(0xffffffffu, sum, 2);
            const float alpha = __expf(m_old - m_new);
            if (sg == 0) {
                msh[srow]  = m_new;
                lsh[srow]  = lsh[srow] * alpha + sum;
                alsh[srow] = alpha;
            }
        }
        __syncthreads();

        // rescale O, then O += P @ V
        #pragma unroll
        for (int i = 0; i < 4; i++) {
            const float al = alsh[ty4 + i];
            #pragma unroll
            for (int j = 0; j < 4; j++) o[i][j] *= al;
        }
        #pragma unroll 4
        for (int kk = 0; kk < 64; kk++) {
            float p[4], v[4];
            #pragma unroll
            for (int i = 0; i < 4; i++) p[i] = Ssh[(ty4 + i) * PAD + kk];
            #pragma unroll
            for (int j = 0; j < 4; j++) v[j] = Vs[kk * PAD + tx4 + j];
            #pragma unroll
            for (int i = 0; i < 4; i++)
                #pragma unroll
                for (int j = 0; j < 4; j++) o[i][j] += p[i] * v[j];
        }
    }

    // write context in [b, q, h*HD+d] layout
    #pragma unroll
    for (int i = 0; i < 4; i++) {
        const int q = q0 + ty4 + i;
        const float inv = 1.0f / lsh[ty4 + i];
        #pragma unroll
        for (int j = 0; j < 4; j++) {
            ctx[((size_t)(b * QLEN + q)) * DIM + h * HD + tx4 + j] = o[i][j] * inv;
        }
    }
}

// ---------------------------------------------------------------------------
extern "C" void kernel_launch(void* const* d_in, const int* in_sizes, int n_in,
                              void* d_out, int out_size)
{
    const float* x    = (const float*)d_in[0];
    const float* mask = (const float*)d_in[1];
    const float* Wq   = (const float*)d_in[2];
    const float* bq   = (const float*)d_in[3];
    const float* Wk   = (const float*)d_in[4];
    const float* bk   = (const float*)d_in[5];
    const float* Wv   = (const float*)d_in[6];
    const float* bv   = (const float*)d_in[7];
    const float* Wo   = (const float*)d_in[8];
    const float* bo   = (const float*)d_in[9];
    float* out = (float*)d_out;

    float *Qp, *Kp, *Vp, *Cp;
    cudaGetSymbolAddress((void**)&Qp, g_Q);
    cudaGetSymbolAddress((void**)&Kp, g_K);
    cudaGetSymbolAddress((void**)&Vp, g_V);
    cudaGetSymbolAddress((void**)&Cp, g_C);

    const dim3 gg(DIM / 128, MTOT / 128);
    const float qscale = 1.0f / sqrtf((float)HD);

    sgemm_bias<1><<<gg, 256>>>(x, Wq, bq, Qp, qscale);
    sgemm_bias<1><<<gg, 256>>>(x, Wk, bk, Kp, 1.0f);
    sgemm_bias<1><<<gg, 256>>>(x, Wv, bv, Vp, 1.0f);

    cudaFuncSetAttribute(attn_kernel, cudaFuncAttributeMaxDynamicSharedMemorySize,
                         SMEM_ATTN_BYTES);
    attn_kernel<<<dim3(BSZ * NH, QLEN / 64), 256, SMEM_ATTN_BYTES>>>(Qp, Kp, Vp, mask, Cp);

    sgemm_bias<0><<<gg, 256>>>(Cp, Wo, bo, out, 1.0f);
}

// round 5
// speedup vs baseline: 1.5498x; 1.5498x over previous
#include <cuda_runtime.h>
#include <cstdint>
#include <math.h>

// Problem dims
#define BSZ   2
#define QLEN  2048
#define DIM   1024
#define NH    16
#define HD    64
#define MTOT  (BSZ*QLEN)   // 4096

// Scratch (device globals: allocation-free)
__device__ float g_Q[BSZ*NH*QLEN*HD];
__device__ float g_K[BSZ*NH*QLEN*HD];
__device__ float g_V[BSZ*NH*QLEN*HD];
__device__ float g_C[MTOT*DIM];
__device__ float g_WqT[DIM*DIM];
__device__ float g_WkT[DIM*DIM];
__device__ float g_WvT[DIM*DIM];
__device__ float g_WoT[DIM*DIM];

__device__ __forceinline__ uint32_t smem_u32(const void* p) {
    uint32_t a;
    asm("{ .reg .u64 t; cvta.to.shared.u64 t, %1; cvt.u32.u64 %0, t; }" : "=r"(a) : "l"(p));
    return a;
}

__device__ __forceinline__ void cp16(uint32_t saddr, const void* gaddr) {
    asm volatile("cp.async.cg.shared.global [%0], [%1], 16;" :: "r"(saddr), "l"(gaddr));
}
__device__ __forceinline__ void cp_commit() {
    asm volatile("cp.async.commit_group;");
}
template<int N>
__device__ __forceinline__ void cp_wait() {
    asm volatile("cp.async.wait_group %0;" :: "n"(N));
}

__device__ __forceinline__ uint32_t f2tf32(float f) {
    uint32_t u;
    asm("cvt.rna.tf32.f32 %0, %1;" : "=r"(u) : "f"(f));
    return u;
}

__device__ __forceinline__ void mma_tf32(float c[4],
    uint32_t a0, uint32_t a1, uint32_t a2, uint32_t a3, uint32_t b0, uint32_t b1)
{
    asm volatile(
        "mma.sync.aligned.m16n8k8.row.col.f32.tf32.tf32.f32 "
        "{%0,%1,%2,%3}, {%4,%5,%6,%7}, {%8,%9}, {%0,%1,%2,%3};"
        : "+f"(c[0]), "+f"(c[1]), "+f"(c[2]), "+f"(c[3])
        : "r"(a0), "r"(a1), "r"(a2), "r"(a3), "r"(b0), "r"(b1));
}

// ---------------------------------------------------------------------------
// 32x32 tiled transpose: out[n*1024+k] = in[k*1024+n]
// ---------------------------------------------------------------------------
__global__ void transpose1024(const float* __restrict__ in, float* __restrict__ out)
{
    __shared__ float tile[32][33];
    int x = blockIdx.x * 32 + threadIdx.x;
    int y = blockIdx.y * 32 + threadIdx.y;
    #pragma unroll
    for (int i = 0; i < 32; i += 8)
        tile[threadIdx.y + i][threadIdx.x] = in[(size_t)(y + i) * DIM + x];
    __syncthreads();
    int x2 = blockIdx.y * 32 + threadIdx.x;
    int y2 = blockIdx.x * 32 + threadIdx.y;
    #pragma unroll
    for (int i = 0; i < 32; i += 8)
        out[(size_t)(y2 + i) * DIM + x2] = tile[threadIdx.x][threadIdx.y + i];
}

// ---------------------------------------------------------------------------
// tf32 mma.sync GEMM: out = (A[M,K] @ Wt[N,K]^T + bias) * scale
// A row-major [4096,1024]; Wt K-major [1024(N),1024(K)] ("col" B layout).
// CTA 128x128, BK=16, 256 threads; warp tile 64x32 (4x4 m16n8k8 tiles).
// MODE 0: row-major out; MODE 1: head-split [b,h,q,d].
// ---------------------------------------------------------------------------
#define BM 128
#define BN 128
#define BK 16
#define PADK 20
#define KTILES (DIM/BK)   // 64

template<int MODE>
__global__ void __launch_bounds__(256) gemm_mma(
    const float* __restrict__ A, const float* __restrict__ Wt,
    const float* __restrict__ bias, float* __restrict__ out, float scale)
{
    __shared__ float As[2][BM * PADK];
    __shared__ float Bs[2][BN * PADK];
    __shared__ float s_bias[BN];

    const int tid  = threadIdx.x;
    const int wid  = tid >> 5;
    const int lane = tid & 31;
    const int g    = lane >> 2;     // group id 0..7
    const int tg   = lane & 3;      // thread-in-group 0..3
    const int wr   = wid >> 2;      // 0..1  -> 64-row slab
    const int wc   = wid & 3;       // 0..3  -> 32-col slab
    const int br   = blockIdx.y * BM;
    const int bc   = blockIdx.x * BN;

    if (tid < BN) s_bias[tid] = bias[bc + tid];

    // Load mapping: 2 float4 per operand per thread.
    int rows[2], k4s[2];
    uint32_t aAddr[2], bAddr[2];
    const float* aPtr[2];
    const float* bPtr[2];
    const uint32_t aBase = smem_u32(As);
    const uint32_t bBase = smem_u32(Bs);
    #pragma unroll
    for (int i = 0; i < 2; i++) {
        int idx = i * 256 + tid;
        int row = idx >> 2;           // 0..127
        int k4  = (idx & 3) * 4;      // 0,4,8,12
        rows[i] = row; k4s[i] = k4;
        aAddr[i] = aBase + (uint32_t)(row * PADK + k4) * 4u;
        bAddr[i] = bBase + (uint32_t)(row * PADK + k4) * 4u;
        aPtr[i]  = A  + (size_t)(br + row) * DIM + k4;
        bPtr[i]  = Wt + (size_t)(bc + row) * DIM + k4;
    }
    const uint32_t stageA = (uint32_t)(BM * PADK) * 4u;
    const uint32_t stageB = (uint32_t)(BN * PADK) * 4u;

    float acc[4][4][4];
    #pragma unroll
    for (int mt = 0; mt < 4; mt++)
        #pragma unroll
        for (int nt = 0; nt < 4; nt++)
            #pragma unroll
            for (int i = 0; i < 4; i++) acc[mt][nt][i] = 0.0f;

    // prologue: stage 0
    #pragma unroll
    for (int i = 0; i < 2; i++) {
        cp16(aAddr[i], aPtr[i]);
        cp16(bAddr[i], bPtr[i]);
    }
    cp_commit();

    for (int kt = 0; kt < KTILES; kt++) {
        const int buf = kt & 1;
        if (kt + 1 < KTILES) {
            const int nb = (kt + 1) & 1;
            const int k0 = (kt + 1) * BK;
            #pragma unroll
            for (int i = 0; i < 2; i++) {
                cp16(aAddr[i] + nb * stageA, aPtr[i] + k0);
                cp16(bAddr[i] + nb * stageB, bPtr[i] + k0);
            }
            cp_commit();
            cp_wait<1>();
        } else {
            cp_wait<0>();
        }
        __syncthreads();

        const float* Ab = As[buf];
        const float* Bb = Bs[buf];
        #pragma unroll
        for (int ks = 0; ks < BK; ks += 8) {
            uint32_t af[4][4];
            #pragma unroll
            for (int mt = 0; mt < 4; mt++) {
                const int r0 = wr * 64 + mt * 16 + g;
                af[mt][0] = f2tf32(Ab[(r0    ) * PADK + ks + tg    ]);
                af[mt][1] = f2tf32(Ab[(r0 + 8) * PADK + ks + tg    ]);
                af[mt][2] = f2tf32(Ab[(r0    ) * PADK + ks + tg + 4]);
                af[mt][3] = f2tf32(Ab[(r0 + 8) * PADK + ks + tg + 4]);
            }
            uint32_t bf[4][2];
            #pragma unroll
            for (int nt = 0; nt < 4; nt++) {
                const int n0 = wc * 32 + nt * 8 + g;
                bf[nt][0] = f2tf32(Bb[n0 * PADK + ks + tg    ]);
                bf[nt][1] = f2tf32(Bb[n0 * PADK + ks + tg + 4]);
            }
            #pragma unroll
            for (int mt = 0; mt < 4; mt++)
                #pragma unroll
                for (int nt = 0; nt < 4; nt++)
                    mma_tf32(acc[mt][nt], af[mt][0], af[mt][1], af[mt][2], af[mt][3],
                             bf[nt][0], bf[nt][1]);
        }
        __syncthreads();
    }

    // epilogue
    #pragma unroll
    for (int mt = 0; mt < 4; mt++) {
        #pragma unroll
        for (int nt = 0; nt < 4; nt++) {
            const int nl = wc * 32 + nt * 8 + tg * 2;   // local col (even)
            const int n  = bc + nl;
            const float b0 = s_bias[nl], b1 = s_bias[nl + 1];
            #pragma unroll
            for (int half = 0; half < 2; half++) {
                const int m = br + wr * 64 + mt * 16 + g + half * 8;
                float2 v;
                v.x = (acc[mt][nt][half * 2 + 0] + b0) * scale;
                v.y = (acc[mt][nt][half * 2 + 1] + b1) * scale;
                if (MODE == 0) {
                    *(float2*)(&out[(size_t)m * DIM + n]) = v;
                } else {
                    const int bb = m >> 11, q = m & 2047, h = n >> 6, d = n & 63;
                    *(float2*)(&out[(((size_t)bb * NH + h) * QLEN + q) * HD + d]) = v;
                }
            }
        }
    }
}

// ---------------------------------------------------------------------------
// Flash attention (fp32 SIMT) — unchanged from R1 (passing).
// ---------------------------------------------------------------------------
#define PAD 65
#define SMEM_ATTN_BYTES ((4*64*PAD + 4*64) * 4)

__global__ void __launch_bounds__(256) attn_kernel(
    const float* __restrict__ Q, const float* __restrict__ K,
    const float* __restrict__ V, const float* __restrict__ mask,
    float* __restrict__ ctx)
{
    extern __shared__ float sm[];
    float* Qs   = sm;
    float* Ks   = Qs  + 64 * PAD;
    float* Vs   = Ks  + 64 * PAD;
    float* Ssh  = Vs  + 64 * PAD;
    float* msh  = Ssh + 64 * PAD;
    float* lsh  = msh + 64;
    float* alsh = lsh + 64;
    float* madd = alsh + 64;

    const int tid = threadIdx.x;
    const int bh  = blockIdx.x;
    const int b   = bh >> 4;
    const int h   = bh & 15;
    const int q0  = blockIdx.y * 64;

    const float* Qh = Q + (size_t)bh * QLEN * HD;
    const float* Kh = K + (size_t)bh * QLEN * HD;
    const float* Vh = V + (size_t)bh * QLEN * HD;
    const float* mb = mask + (size_t)b * QLEN;

    const int ty  = tid >> 4;
    const int tx  = tid & 15;
    const int ty4 = ty * 4;
    const int tx4 = tx * 4;
    const int srow = tid >> 2;
    const int sg   = tid & 3;

    #pragma unroll
    for (int it = 0; it < 16; it++) {
        int idx = tid + it * 256;
        int r = idx >> 6, c = idx & 63;
        Qs[r * PAD + c] = Qh[(size_t)(q0 + r) * HD + c];
    }
    if (tid < 64) { msh[tid] = -1e30f; lsh[tid] = 0.0f; }

    float o[4][4];
    #pragma unroll
    for (int i = 0; i < 4; i++)
        #pragma unroll
        for (int j = 0; j < 4; j++) o[i][j] = 0.0f;

    for (int t = 0; t < QLEN / 64; t++) {
        const int kk0 = t * 64;
        __syncthreads();

        #pragma unroll
        for (int it = 0; it < 16; it++) {
            int idx = tid + it * 256;
            int r = idx >> 6, c = idx & 63;
            Ks[r * PAD + c] = Kh[(size_t)(kk0 + r) * HD + c];
            Vs[r * PAD + c] = Vh[(size_t)(kk0 + r) * HD + c];
        }
        if (tid < 64) madd[tid] = -1e30f * (1.0f - mb[kk0 + tid]);
        __syncthreads();

        float s[4][4];
        #pragma unroll
        for (int i = 0; i < 4; i++)
            #pragma unroll
            for (int j = 0; j < 4; j++) s[i][j] = 0.0f;

        #pragma unroll 4
        for (int kk = 0; kk < 64; kk++) {
            float a[4], bb[4];
            #pragma unroll
            for (int i = 0; i < 4; i++) a[i]  = Qs[(ty4 + i) * PAD + kk];
            #pragma unroll
            for (int j = 0; j < 4; j++) bb[j] = Ks[(tx4 + j) * PAD + kk];
            #pragma unroll
            for (int i = 0; i < 4; i++)
                #pragma unroll
                for (int j = 0; j < 4; j++) s[i][j] += a[i] * bb[j];
        }
        #pragma unroll
        for (int i = 0; i < 4; i++)
            #pragma unroll
            for (int j = 0; j < 4; j++)
                Ssh[(ty4 + i) * PAD + tx4 + j] = s[i][j] + madd[tx4 + j];
        __syncthreads();

        {
            float tmax = -1e30f;
            for (int c = sg; c < 64; c += 4)
                tmax = fmaxf(tmax, Ssh[srow * PAD + c]);
            tmax = fmaxf(tmax, __shfl_xor_sync(0xffffffffu, tmax, 1));
            tmax = fmaxf(tmax, __shfl_xor_sync(0xffffffffu, tmax, 2));

            const float m_old = msh[srow];
            const float m_new = fmaxf(m_old, tmax);
            float sum = 0.0f;
            for (int c = sg; c < 64; c += 4) {
                float p = __expf(Ssh[srow * PAD + c] - m_new);
                Ssh[srow * PAD + c] = p;
                sum += p;
            }
            sum += __shfl_xor_sync(0xffffffffu, sum, 1);
            sum += __shfl_xor_sync(0xffffffffu, sum, 2);
            const float alpha = __expf(m_old - m_new);
            if (sg == 0) {
                msh[srow]  = m_new;
                lsh[srow]  = lsh[srow] * alpha + sum;
                alsh[srow] = alpha;
            }
        }
        __syncthreads();

        #pragma unroll
        for (int i = 0; i < 4; i++) {
            const float al = alsh[ty4 + i];
            #pragma unroll
            for (int j = 0; j < 4; j++) o[i][j] *= al;
        }
        #pragma unroll 4
        for (int kk = 0; kk < 64; kk++) {
            float p[4], v[4];
            #pragma unroll
            for (int i = 0; i < 4; i++) p[i] = Ssh[(ty4 + i) * PAD + kk];
            #pragma unroll
            for (int j = 0; j < 4; j++) v[j] = Vs[kk * PAD + tx4 + j];
            #pragma unroll
            for (int i = 0; i < 4; i++)
                #pragma unroll
                for (int j = 0; j < 4; j++) o[i][j] += p[i] * v[j];
        }
    }

    #pragma unroll
    for (int i = 0; i < 4; i++) {
        const int q = q0 + ty4 + i;
        const float inv = 1.0f / lsh[ty4 + i];
        #pragma unroll
        for (int j = 0; j < 4; j++) {
            ctx[((size_t)(b * QLEN + q)) * DIM + h * HD + tx4 + j] = o[i][j] * inv;
        }
    }
}

// ---------------------------------------------------------------------------
extern "C" void kernel_launch(void* const* d_in, const int* in_sizes, int n_in,
                              void* d_out, int out_size)
{
    const float* x    = (const float*)d_in[0];
    const float* mask = (const float*)d_in[1];
    const float* Wq   = (const float*)d_in[2];
    const float* bq   = (const float*)d_in[3];
    const float* Wk   = (const float*)d_in[4];
    const float* bk   = (const float*)d_in[5];
    const float* Wv   = (const float*)d_in[6];
    const float* bv   = (const float*)d_in[7];
    const float* Wo   = (const float*)d_in[8];
    const float* bo   = (const float*)d_in[9];
    float* out = (float*)d_out;

    float *Qp, *Kp, *Vp, *Cp, *WqT, *WkT, *WvT, *WoT;
    cudaGetSymbolAddress((void**)&Qp, g_Q);
    cudaGetSymbolAddress((void**)&Kp, g_K);
    cudaGetSymbolAddress((void**)&Vp, g_V);
    cudaGetSymbolAddress((void**)&Cp, g_C);
    cudaGetSymbolAddress((void**)&WqT, g_WqT);
    cudaGetSymbolAddress((void**)&WkT, g_WkT);
    cudaGetSymbolAddress((void**)&WvT, g_WvT);
    cudaGetSymbolAddress((void**)&WoT, g_WoT);

    const dim3 tg(32, 32), tb(32, 8);
    transpose1024<<<tg, tb>>>(Wq, WqT);
    transpose1024<<<tg, tb>>>(Wk, WkT);
    transpose1024<<<tg, tb>>>(Wv, WvT);
    transpose1024<<<tg, tb>>>(Wo, WoT);

    const dim3 gg(DIM / 128, MTOT / 128);   // (8, 32)
    const float qscale = 1.0f / sqrtf((float)HD);

    gemm_mma<1><<<gg, 256>>>(x, WqT, bq, Qp, qscale);
    gemm_mma<1><<<gg, 256>>>(x, WkT, bk, Kp, 1.0f);
    gemm_mma<1><<<gg, 256>>>(x, WvT, bv, Vp, 1.0f);

    cudaFuncSetAttribute(attn_kernel, cudaFuncAttributeMaxDynamicSharedMemorySize,
                         SMEM_ATTN_BYTES);
    attn_kernel<<<dim3(BSZ * NH, QLEN / 64), 256, SMEM_ATTN_BYTES>>>(Qp, Kp, Vp, mask, Cp);

    gemm_mma<0><<<gg, 256>>>(Cp, WoT, bo, out, 1.0f);
}

// round 6
// speedup vs baseline: 3.1260x; 2.0170x over previous
#include <cuda_runtime.h>
#include <cstdint>
#include <math.h>

// Problem dims
#define BSZ   2
#define QLEN  2048
#define DIM   1024
#define NH    16
#define HD    64
#define MTOT  (BSZ*QLEN)   // 4096

// Scratch (device globals: allocation-free)
__device__ float g_Q[BSZ*NH*QLEN*HD];
__device__ float g_K[BSZ*NH*QLEN*HD];
__device__ float g_V[BSZ*NH*QLEN*HD];
__device__ float g_C[MTOT*DIM];
__device__ float g_WqT[DIM*DIM];
__device__ float g_WkT[DIM*DIM];
__device__ float g_WvT[DIM*DIM];
__device__ float g_WoT[DIM*DIM];

__device__ __forceinline__ uint32_t smem_u32(const void* p) {
    uint32_t a;
    asm("{ .reg .u64 t; cvta.to.shared.u64 t, %1; cvt.u32.u64 %0, t; }" : "=r"(a) : "l"(p));
    return a;
}
__device__ __forceinline__ void cp16(uint32_t saddr, const void* gaddr) {
    asm volatile("cp.async.cg.shared.global [%0], [%1], 16;" :: "r"(saddr), "l"(gaddr));
}
__device__ __forceinline__ void cp_commit() { asm volatile("cp.async.commit_group;"); }
template<int N>
__device__ __forceinline__ void cp_wait() { asm volatile("cp.async.wait_group %0;" :: "n"(N)); }

__device__ __forceinline__ uint32_t f2tf32(float f) {
    uint32_t u;
    asm("cvt.rna.tf32.f32 %0, %1;" : "=r"(u) : "f"(f));
    return u;
}
__device__ __forceinline__ void mma_tf32(float c[4],
    uint32_t a0, uint32_t a1, uint32_t a2, uint32_t a3, uint32_t b0, uint32_t b1)
{
    asm volatile(
        "mma.sync.aligned.m16n8k8.row.col.f32.tf32.tf32.f32 "
        "{%0,%1,%2,%3}, {%4,%5,%6,%7}, {%8,%9}, {%0,%1,%2,%3};"
        : "+f"(c[0]), "+f"(c[1]), "+f"(c[2]), "+f"(c[3])
        : "r"(a0), "r"(a1), "r"(a2), "r"(a3), "r"(b0), "r"(b1));
}

// ---------------------------------------------------------------------------
// 32x32 tiled transpose
// ---------------------------------------------------------------------------
__global__ void transpose1024(const float* __restrict__ in, float* __restrict__ out)
{
    __shared__ float tile[32][33];
    int x = blockIdx.x * 32 + threadIdx.x;
    int y = blockIdx.y * 32 + threadIdx.y;
    #pragma unroll
    for (int i = 0; i < 32; i += 8)
        tile[threadIdx.y + i][threadIdx.x] = in[(size_t)(y + i) * DIM + x];
    __syncthreads();
    int x2 = blockIdx.y * 32 + threadIdx.x;
    int y2 = blockIdx.x * 32 + threadIdx.y;
    #pragma unroll
    for (int i = 0; i < 32; i += 8)
        out[(size_t)(y2 + i) * DIM + x2] = tile[threadIdx.x][threadIdx.y + i];
}

// ---------------------------------------------------------------------------
// tf32 mma.sync GEMM (unchanged from R5, passing)
// ---------------------------------------------------------------------------
#define BM 128
#define BN 128
#define BK 16
#define PADK 20
#define KTILES (DIM/BK)

template<int MODE>
__global__ void __launch_bounds__(256) gemm_mma(
    const float* __restrict__ A, const float* __restrict__ Wt,
    const float* __restrict__ bias, float* __restrict__ out, float scale)
{
    __shared__ float As[2][BM * PADK];
    __shared__ float Bs[2][BN * PADK];
    __shared__ float s_bias[BN];

    const int tid  = threadIdx.x;
    const int wid  = tid >> 5;
    const int lane = tid & 31;
    const int g    = lane >> 2;
    const int tg   = lane & 3;
    const int wr   = wid >> 2;
    const int wc   = wid & 3;
    const int br   = blockIdx.y * BM;
    const int bc   = blockIdx.x * BN;

    if (tid < BN) s_bias[tid] = bias[bc + tid];

    uint32_t aAddr[2], bAddr[2];
    const float* aPtr[2];
    const float* bPtr[2];
    const uint32_t aBase = smem_u32(As);
    const uint32_t bBase = smem_u32(Bs);
    #pragma unroll
    for (int i = 0; i < 2; i++) {
        int idx = i * 256 + tid;
        int row = idx >> 2;
        int k4  = (idx & 3) * 4;
        aAddr[i] = aBase + (uint32_t)(row * PADK + k4) * 4u;
        bAddr[i] = bBase + (uint32_t)(row * PADK + k4) * 4u;
        aPtr[i]  = A  + (size_t)(br + row) * DIM + k4;
        bPtr[i]  = Wt + (size_t)(bc + row) * DIM + k4;
    }
    const uint32_t stageA = (uint32_t)(BM * PADK) * 4u;
    const uint32_t stageB = (uint32_t)(BN * PADK) * 4u;

    float acc[4][4][4];
    #pragma unroll
    for (int mt = 0; mt < 4; mt++)
        #pragma unroll
        for (int nt = 0; nt < 4; nt++)
            #pragma unroll
            for (int i = 0; i < 4; i++) acc[mt][nt][i] = 0.0f;

    #pragma unroll
    for (int i = 0; i < 2; i++) { cp16(aAddr[i], aPtr[i]); cp16(bAddr[i], bPtr[i]); }
    cp_commit();

    for (int kt = 0; kt < KTILES; kt++) {
        const int buf = kt & 1;
        if (kt + 1 < KTILES) {
            const int nb = (kt + 1) & 1;
            const int k0 = (kt + 1) * BK;
            #pragma unroll
            for (int i = 0; i < 2; i++) {
                cp16(aAddr[i] + nb * stageA, aPtr[i] + k0);
                cp16(bAddr[i] + nb * stageB, bPtr[i] + k0);
            }
            cp_commit();
            cp_wait<1>();
        } else {
            cp_wait<0>();
        }
        __syncthreads();

        const float* Ab = As[buf];
        const float* Bb = Bs[buf];
        #pragma unroll
        for (int ks = 0; ks < BK; ks += 8) {
            uint32_t af[4][4];
            #pragma unroll
            for (int mt = 0; mt < 4; mt++) {
                const int r0 = wr * 64 + mt * 16 + g;
                af[mt][0] = f2tf32(Ab[(r0    ) * PADK + ks + tg    ]);
                af[mt][1] = f2tf32(Ab[(r0 + 8) * PADK + ks + tg    ]);
                af[mt][2] = f2tf32(Ab[(r0    ) * PADK + ks + tg + 4]);
                af[mt][3] = f2tf32(Ab[(r0 + 8) * PADK + ks + tg + 4]);
            }
            uint32_t bf[4][2];
            #pragma unroll
            for (int nt = 0; nt < 4; nt++) {
                const int n0 = wc * 32 + nt * 8 + g;
                bf[nt][0] = f2tf32(Bb[n0 * PADK + ks + tg    ]);
                bf[nt][1] = f2tf32(Bb[n0 * PADK + ks + tg + 4]);
            }
            #pragma unroll
            for (int mt = 0; mt < 4; mt++)
                #pragma unroll
                for (int nt = 0; nt < 4; nt++)
                    mma_tf32(acc[mt][nt], af[mt][0], af[mt][1], af[mt][2], af[mt][3],
                             bf[nt][0], bf[nt][1]);
        }
        __syncthreads();
    }

    #pragma unroll
    for (int mt = 0; mt < 4; mt++) {
        #pragma unroll
        for (int nt = 0; nt < 4; nt++) {
            const int nl = wc * 32 + nt * 8 + tg * 2;
            const int n  = bc + nl;
            const float b0 = s_bias[nl], b1 = s_bias[nl + 1];
            #pragma unroll
            for (int half = 0; half < 2; half++) {
                const int m = br + wr * 64 + mt * 16 + g + half * 8;
                float2 v;
                v.x = (acc[mt][nt][half * 2 + 0] + b0) * scale;
                v.y = (acc[mt][nt][half * 2 + 1] + b1) * scale;
                if (MODE == 0) {
                    *(float2*)(&out[(size_t)m * DIM + n]) = v;
                } else {
                    const int bb = m >> 11, q = m & 2047, h = n >> 6, d = n & 63;
                    *(float2*)(&out[(((size_t)bb * NH + h) * QLEN + q) * HD + d]) = v;
                }
            }
        }
    }
}

// ---------------------------------------------------------------------------
// Tensor-core flash attention (tf32 mma.sync; V hi/lo split for accuracy).
// Block = (batch*head, 64-query tile). 256 threads = 8 warps: wr=wid>>1 (16-row
// slab), wc=wid&1 (32-col slab). S and P tiles in smem pad 68; K pad 68;
// Vhi/Vlo pad 72 (conflict-free B-fragment gathers).
// ---------------------------------------------------------------------------
#define PA 68
#define PV 72
#define ATTN_SMEM ((3*64*PA + 2*64*PV + 4*64) * 4)

__global__ void __launch_bounds__(256) attn_mma(
    const float* __restrict__ Q, const float* __restrict__ K,
    const float* __restrict__ V, const float* __restrict__ mask,
    float* __restrict__ ctx)
{
    extern __shared__ unsigned char smraw[];
    uint32_t* Qs  = (uint32_t*)smraw;                         // 64 x PA (tf32)
    float*    Ssh = (float*)(smraw + (64*PA)*4);              // 64 x PA
    float*    Ks  = (float*)(smraw + (2*64*PA)*4);            // 64 x PA (raw f32)
    uint32_t* Vhi = (uint32_t*)(smraw + (3*64*PA)*4);         // 64 x PV (tf32)
    uint32_t* Vlo = Vhi + 64*PV;                              // 64 x PV (tf32)
    float*    msh  = (float*)(Vlo + 64*PV);
    float*    lsh  = msh + 64;
    float*    alsh = lsh + 64;
    float*    madd = alsh + 64;

    const int tid  = threadIdx.x;
    const int wid  = tid >> 5;
    const int lane = tid & 31;
    const int g    = lane >> 2;
    const int tg   = lane & 3;
    const int wr   = wid >> 1;          // 0..3
    const int wc   = wid & 1;           // 0..1
    const int rb   = wr * 16;

    const int bh = blockIdx.x;          // 0..31
    const int b  = bh >> 4;
    const int h  = bh & 15;
    const int q0 = blockIdx.y * 64;

    const float* Qh = Q + (size_t)bh * QLEN * HD;
    const float* Kh = K + (size_t)bh * QLEN * HD;
    const float* Vh = V + (size_t)bh * QLEN * HD;
    const float* mb = mask + (size_t)b * QLEN;

    const uint32_t ksBase = smem_u32(Ks);

    // stage Q (tf32, pre-scaled by projection)
    #pragma unroll
    for (int i = 0; i < 16; i++) {
        int idx = tid + i * 256;
        int r = idx >> 6, c = idx & 63;
        Qs[r * PA + c] = f2tf32(Qh[(size_t)(q0 + r) * HD + c]);
    }
    if (tid < 64) { msh[tid] = -1e30f; lsh[tid] = 0.0f; }

    float o[4][4];
    #pragma unroll
    for (int nt = 0; nt < 4; nt++)
        #pragma unroll
        for (int i = 0; i < 4; i++) o[nt][i] = 0.0f;

    for (int t = 0; t < QLEN / 64; t++) {
        const int kk0 = t * 64;
        __syncthreads();     // prev PV done before restaging

        // K via cp.async
        #pragma unroll
        for (int i = 0; i < 4; i++) {
            int idx = tid + i * 256;
            int r = idx >> 4, c4 = (idx & 15) * 4;
            cp16(ksBase + (uint32_t)(r * PA + c4) * 4u, Kh + (size_t)(kk0 + r) * HD + c4);
        }
        cp_commit();
        // V: load, hi/lo split, store
        #pragma unroll
        for (int i = 0; i < 4; i++) {
            int idx = tid + i * 256;
            int r = idx >> 4, c4 = (idx & 15) * 4;
            float4 v = *(const float4*)(Vh + (size_t)(kk0 + r) * HD + c4);
            uint4 hi, lo;
            hi.x = f2tf32(v.x); lo.x = f2tf32(v.x - __uint_as_float(hi.x));
            hi.y = f2tf32(v.y); lo.y = f2tf32(v.y - __uint_as_float(hi.y));
            hi.z = f2tf32(v.z); lo.z = f2tf32(v.z - __uint_as_float(hi.z));
            hi.w = f2tf32(v.w); lo.w = f2tf32(v.w - __uint_as_float(hi.w));
            *(uint4*)(&Vhi[r * PV + c4]) = hi;
            *(uint4*)(&Vlo[r * PV + c4]) = lo;
        }
        if (tid < 64) madd[tid] = -1e30f * (1.0f - mb[kk0 + tid]);
        cp_wait<0>();
        __syncthreads();

        // S = Q @ K^T (this warp: rows rb..rb+15, keys wc*32..+31)
        float sacc[4][4];
        #pragma unroll
        for (int nt = 0; nt < 4; nt++)
            #pragma unroll
            for (int i = 0; i < 4; i++) sacc[nt][i] = 0.0f;

        #pragma unroll
        for (int ks = 0; ks < 8; ks++) {
            const int k = ks * 8;
            uint32_t a0 = Qs[(rb + g    ) * PA + k + tg    ];
            uint32_t a1 = Qs[(rb + g + 8) * PA + k + tg    ];
            uint32_t a2 = Qs[(rb + g    ) * PA + k + tg + 4];
            uint32_t a3 = Qs[(rb + g + 8) * PA + k + tg + 4];
            #pragma unroll
            for (int nt = 0; nt < 4; nt++) {
                const int n0 = wc * 32 + nt * 8 + g;
                uint32_t b0 = f2tf32(Ks[n0 * PA + k + tg    ]);
                uint32_t b1 = f2tf32(Ks[n0 * PA + k + tg + 4]);
                mma_tf32(sacc[nt], a0, a1, a2, a3, b0, b1);
            }
        }
        #pragma unroll
        for (int nt = 0; nt < 4; nt++) {
            const int col = wc * 32 + nt * 8 + tg * 2;
            Ssh[(rb + g    ) * PA + col    ] = sacc[nt][0] + madd[col];
            Ssh[(rb + g    ) * PA + col + 1] = sacc[nt][1] + madd[col + 1];
            Ssh[(rb + g + 8) * PA + col    ] = sacc[nt][2] + madd[col];
            Ssh[(rb + g + 8) * PA + col + 1] = sacc[nt][3] + madd[col + 1];
        }
        __syncthreads();

        // online softmax: 4 threads per row
        {
            const int row = tid >> 2;
            const int sg  = tid & 3;
            float tmax = -1e30f;
            #pragma unroll
            for (int c = 0; c < 16; c++)
                tmax = fmaxf(tmax, Ssh[row * PA + sg + c * 4]);
            tmax = fmaxf(tmax, __shfl_xor_sync(0xffffffffu, tmax, 1));
            tmax = fmaxf(tmax, __shfl_xor_sync(0xffffffffu, tmax, 2));
            const float m_old = msh[row];
            const float m_new = fmaxf(m_old, tmax);
            float sum = 0.0f;
            #pragma unroll
            for (int c = 0; c < 16; c++) {
                float p = __expf(Ssh[row * PA + sg + c * 4] - m_new);
                Ssh[row * PA + sg + c * 4] = p;
                sum += p;
            }
            sum += __shfl_xor_sync(0xffffffffu, sum, 1);
            sum += __shfl_xor_sync(0xffffffffu, sum, 2);
            if (sg == 0) {
                const float alpha = __expf(m_old - m_new);
                msh[row]  = m_new;
                lsh[row]  = lsh[row] * alpha + sum;
                alsh[row] = alpha;
            }
        }
        __syncthreads();

        // rescale O, then O += P @ (Vhi + Vlo)
        {
            const float a_lo = alsh[rb + g];
            const float a_hi = alsh[rb + g + 8];
            #pragma unroll
            for (int nt = 0; nt < 4; nt++) {
                o[nt][0] *= a_lo; o[nt][1] *= a_lo;
                o[nt][2] *= a_hi; o[nt][3] *= a_hi;
            }
        }
        #pragma unroll
        for (int ks = 0; ks < 8; ks++) {
            const int k = ks * 8;
            uint32_t a0 = f2tf32(Ssh[(rb + g    ) * PA + k + tg    ]);
            uint32_t a1 = f2tf32(Ssh[(rb + g + 8) * PA + k + tg    ]);
            uint32_t a2 = f2tf32(Ssh[(rb + g    ) * PA + k + tg + 4]);
            uint32_t a3 = f2tf32(Ssh[(rb + g + 8) * PA + k + tg + 4]);
            #pragma unroll
            for (int nt = 0; nt < 4; nt++) {
                const int d0 = wc * 32 + nt * 8 + g;
                uint32_t bh0 = Vhi[(k + tg    ) * PV + d0];
                uint32_t bh1 = Vhi[(k + tg + 4) * PV + d0];
                mma_tf32(o[nt], a0, a1, a2, a3, bh0, bh1);
                uint32_t bl0 = Vlo[(k + tg    ) * PV + d0];
                uint32_t bl1 = Vlo[(k + tg + 4) * PV + d0];
                mma_tf32(o[nt], a0, a1, a2, a3, bl0, bl1);
            }
        }
    }

    // write context [b, q, h*HD + d]
    const float inv_lo = 1.0f / lsh[rb + g];
    const float inv_hi = 1.0f / lsh[rb + g + 8];
    #pragma unroll
    for (int nt = 0; nt < 4; nt++) {
        const int d = h * HD + wc * 32 + nt * 8 + tg * 2;
        const int m0 = q0 + rb + g;
        float2 v0; v0.x = o[nt][0] * inv_lo; v0.y = o[nt][1] * inv_lo;
        *(float2*)(&ctx[((size_t)(b * QLEN + m0)) * DIM + d]) = v0;
        float2 v1; v1.x = o[nt][2] * inv_hi; v1.y = o[nt][3] * inv_hi;
        *(float2*)(&ctx[((size_t)(b * QLEN + m0 + 8)) * DIM + d]) = v1;
    }
}

// ---------------------------------------------------------------------------
extern "C" void kernel_launch(void* const* d_in, const int* in_sizes, int n_in,
                              void* d_out, int out_size)
{
    const float* x    = (const float*)d_in[0];
    const float* mask = (const float*)d_in[1];
    const float* Wq   = (const float*)d_in[2];
    const float* bq   = (const float*)d_in[3];
    const float* Wk   = (const float*)d_in[4];
    const float* bk   = (const float*)d_in[5];
    const float* Wv   = (const float*)d_in[6];
    const float* bv   = (const float*)d_in[7];
    const float* Wo   = (const float*)d_in[8];
    const float* bo   = (const float*)d_in[9];
    float* out = (float*)d_out;

    float *Qp, *Kp, *Vp, *Cp, *WqT, *WkT, *WvT, *WoT;
    cudaGetSymbolAddress((void**)&Qp, g_Q);
    cudaGetSymbolAddress((void**)&Kp, g_K);
    cudaGetSymbolAddress((void**)&Vp, g_V);
    cudaGetSymbolAddress((void**)&Cp, g_C);
    cudaGetSymbolAddress((void**)&WqT, g_WqT);
    cudaGetSymbolAddress((void**)&WkT, g_WkT);
    cudaGetSymbolAddress((void**)&WvT, g_WvT);
    cudaGetSymbolAddress((void**)&WoT, g_WoT);

    const dim3 tg(32, 32), tb(32, 8);
    transpose1024<<<tg, tb>>>(Wq, WqT);
    transpose1024<<<tg, tb>>>(Wk, WkT);
    transpose1024<<<tg, tb>>>(Wv, WvT);
    transpose1024<<<tg, tb>>>(Wo, WoT);

    const dim3 gg(DIM / 128, MTOT / 128);
    const float qscale = 1.0f / sqrtf((float)HD);

    gemm_mma<1><<<gg, 256>>>(x, WqT, bq, Qp, qscale);
    gemm_mma<1><<<gg, 256>>>(x, WkT, bk, Kp, 1.0f);
    gemm_mma<1><<<gg, 256>>>(x, WvT, bv, Vp, 1.0f);

    cudaFuncSetAttribute(attn_mma, cudaFuncAttributeMaxDynamicSharedMemorySize, ATTN_SMEM);
    attn_mma<<<dim3(BSZ * NH, QLEN / 64), 256, ATTN_SMEM>>>(Qp, Kp, Vp, mask, Cp);

    gemm_mma<0><<<gg, 256>>>(Cp, WoT, bo, out, 1.0f);
}

// round 7
// speedup vs baseline: 3.6007x; 1.1519x over previous
#include <cuda_runtime.h>
#include <cstdint>
#include <math.h>

// Problem dims
#define BSZ   2
#define QLEN  2048
#define DIM   1024
#define NH    16
#define HD    64
#define MTOT  (BSZ*QLEN)   // 4096

// Scratch (device globals: allocation-free)
__device__ float g_Q[BSZ*NH*QLEN*HD];
__device__ float g_K[BSZ*NH*QLEN*HD];
__device__ float g_V[BSZ*NH*QLEN*HD];
__device__ float g_C[MTOT*DIM];
__device__ float g_WqT[DIM*DIM];
__device__ float g_WkT[DIM*DIM];
__device__ float g_WvT[DIM*DIM];
__device__ float g_WoT[DIM*DIM];

__device__ __forceinline__ uint32_t smem_u32(const void* p) {
    uint32_t a;
    asm("{ .reg .u64 t; cvta.to.shared.u64 t, %1; cvt.u32.u64 %0, t; }" : "=r"(a) : "l"(p));
    return a;
}
__device__ __forceinline__ void cp16(uint32_t saddr, const void* gaddr) {
    asm volatile("cp.async.cg.shared.global [%0], [%1], 16;" :: "r"(saddr), "l"(gaddr));
}
__device__ __forceinline__ void cp_commit() { asm volatile("cp.async.commit_group;"); }
template<int N>
__device__ __forceinline__ void cp_wait() { asm volatile("cp.async.wait_group %0;" :: "n"(N)); }

__device__ __forceinline__ uint32_t f2tf32(float f) {
    uint32_t u;
    asm("cvt.rna.tf32.f32 %0, %1;" : "=r"(u) : "f"(f));
    return u;
}
__device__ __forceinline__ void mma_tf32(float c[4],
    uint32_t a0, uint32_t a1, uint32_t a2, uint32_t a3, uint32_t b0, uint32_t b1)
{
    asm volatile(
        "mma.sync.aligned.m16n8k8.row.col.f32.tf32.tf32.f32 "
        "{%0,%1,%2,%3}, {%4,%5,%6,%7}, {%8,%9}, {%0,%1,%2,%3};"
        : "+f"(c[0]), "+f"(c[1]), "+f"(c[2]), "+f"(c[3])
        : "r"(a0), "r"(a1), "r"(a2), "r"(a3), "r"(b0), "r"(b1));
}

// ---------------------------------------------------------------------------
// 32x32 tiled transpose
// ---------------------------------------------------------------------------
__global__ void transpose1024(const float* __restrict__ in, float* __restrict__ out)
{
    __shared__ float tile[32][33];
    int x = blockIdx.x * 32 + threadIdx.x;
    int y = blockIdx.y * 32 + threadIdx.y;
    #pragma unroll
    for (int i = 0; i < 32; i += 8)
        tile[threadIdx.y + i][threadIdx.x] = in[(size_t)(y + i) * DIM + x];
    __syncthreads();
    int x2 = blockIdx.y * 32 + threadIdx.x;
    int y2 = blockIdx.x * 32 + threadIdx.y;
    #pragma unroll
    for (int i = 0; i < 32; i += 8)
        out[(size_t)(y2 + i) * DIM + x2] = tile[threadIdx.x][threadIdx.y + i];
}

// ---------------------------------------------------------------------------
// tf32 mma.sync GEMM (unchanged from R5/R6, passing)
// ---------------------------------------------------------------------------
#define BM 128
#define BN 128
#define BK 16
#define PADK 20
#define KTILES (DIM/BK)

template<int MODE>
__global__ void __launch_bounds__(256) gemm_mma(
    const float* __restrict__ A, const float* __restrict__ Wt,
    const float* __restrict__ bias, float* __restrict__ out, float scale)
{
    __shared__ float As[2][BM * PADK];
    __shared__ float Bs[2][BN * PADK];
    __shared__ float s_bias[BN];

    const int tid  = threadIdx.x;
    const int wid  = tid >> 5;
    const int lane = tid & 31;
    const int g    = lane >> 2;
    const int tg   = lane & 3;
    const int wr   = wid >> 2;
    const int wc   = wid & 3;
    const int br   = blockIdx.y * BM;
    const int bc   = blockIdx.x * BN;

    if (tid < BN) s_bias[tid] = bias[bc + tid];

    uint32_t aAddr[2], bAddr[2];
    const float* aPtr[2];
    const float* bPtr[2];
    const uint32_t aBase = smem_u32(As);
    const uint32_t bBase = smem_u32(Bs);
    #pragma unroll
    for (int i = 0; i < 2; i++) {
        int idx = i * 256 + tid;
        int row = idx >> 2;
        int k4  = (idx & 3) * 4;
        aAddr[i] = aBase + (uint32_t)(row * PADK + k4) * 4u;
        bAddr[i] = bBase + (uint32_t)(row * PADK + k4) * 4u;
        aPtr[i]  = A  + (size_t)(br + row) * DIM + k4;
        bPtr[i]  = Wt + (size_t)(bc + row) * DIM + k4;
    }
    const uint32_t stageA = (uint32_t)(BM * PADK) * 4u;
    const uint32_t stageB = (uint32_t)(BN * PADK) * 4u;

    float acc[4][4][4];
    #pragma unroll
    for (int mt = 0; mt < 4; mt++)
        #pragma unroll
        for (int nt = 0; nt < 4; nt++)
            #pragma unroll
            for (int i = 0; i < 4; i++) acc[mt][nt][i] = 0.0f;

    #pragma unroll
    for (int i = 0; i < 2; i++) { cp16(aAddr[i], aPtr[i]); cp16(bAddr[i], bPtr[i]); }
    cp_commit();

    for (int kt = 0; kt < KTILES; kt++) {
        const int buf = kt & 1;
        if (kt + 1 < KTILES) {
            const int nb = (kt + 1) & 1;
            const int k0 = (kt + 1) * BK;
            #pragma unroll
            for (int i = 0; i < 2; i++) {
                cp16(aAddr[i] + nb * stageA, aPtr[i] + k0);
                cp16(bAddr[i] + nb * stageB, bPtr[i] + k0);
            }
            cp_commit();
            cp_wait<1>();
        } else {
            cp_wait<0>();
        }
        __syncthreads();

        const float* Ab = As[buf];
        const float* Bb = Bs[buf];
        #pragma unroll
        for (int ks = 0; ks < BK; ks += 8) {
            uint32_t af[4][4];
            #pragma unroll
            for (int mt = 0; mt < 4; mt++) {
                const int r0 = wr * 64 + mt * 16 + g;
                af[mt][0] = f2tf32(Ab[(r0    ) * PADK + ks + tg    ]);
                af[mt][1] = f2tf32(Ab[(r0 + 8) * PADK + ks + tg    ]);
                af[mt][2] = f2tf32(Ab[(r0    ) * PADK + ks + tg + 4]);
                af[mt][3] = f2tf32(Ab[(r0 + 8) * PADK + ks + tg + 4]);
            }
            uint32_t bf[4][2];
            #pragma unroll
            for (int nt = 0; nt < 4; nt++) {
                const int n0 = wc * 32 + nt * 8 + g;
                bf[nt][0] = f2tf32(Bb[n0 * PADK + ks + tg    ]);
                bf[nt][1] = f2tf32(Bb[n0 * PADK + ks + tg + 4]);
            }
            #pragma unroll
            for (int mt = 0; mt < 4; mt++)
                #pragma unroll
                for (int nt = 0; nt < 4; nt++)
                    mma_tf32(acc[mt][nt], af[mt][0], af[mt][1], af[mt][2], af[mt][3],
                             bf[nt][0], bf[nt][1]);
        }
        __syncthreads();
    }

    #pragma unroll
    for (int mt = 0; mt < 4; mt++) {
        #pragma unroll
        for (int nt = 0; nt < 4; nt++) {
            const int nl = wc * 32 + nt * 8 + tg * 2;
            const int n  = bc + nl;
            const float b0 = s_bias[nl], b1 = s_bias[nl + 1];
            #pragma unroll
            for (int half = 0; half < 2; half++) {
                const int m = br + wr * 64 + mt * 16 + g + half * 8;
                float2 v;
                v.x = (acc[mt][nt][half * 2 + 0] + b0) * scale;
                v.y = (acc[mt][nt][half * 2 + 1] + b1) * scale;
                if (MODE == 0) {
                    *(float2*)(&out[(size_t)m * DIM + n]) = v;
                } else {
                    const int bb = m >> 11, q = m & 2047, h = n >> 6, d = n & 63;
                    *(float2*)(&out[(((size_t)bb * NH + h) * QLEN + q) * HD + d]) = v;
                }
            }
        }
    }
}

// ---------------------------------------------------------------------------
// Tensor-core flash attention (tf32), single-V (no lo compensation).
// All operands pre-converted to tf32 at staging; softmax emits tf32 P.
// Inner loops are pure LDS + MMA.
// ---------------------------------------------------------------------------
#define PA 68
#define PV 72
#define ATTN_SMEM ((3*64*PA + 64*PV + 4*64) * 4)

__global__ void __launch_bounds__(256) attn_mma(
    const float* __restrict__ Q, const float* __restrict__ K,
    const float* __restrict__ V, const float* __restrict__ mask,
    float* __restrict__ ctx)
{
    extern __shared__ unsigned char smraw[];
    uint32_t* Qs  = (uint32_t*)smraw;                         // 64 x PA (tf32)
    float*    Ssh = (float*)(smraw + (64*PA)*4);              // 64 x PA (scores -> tf32 P)
    uint32_t* Ks  = (uint32_t*)(smraw + (2*64*PA)*4);         // 64 x PA (tf32)
    uint32_t* Vs  = (uint32_t*)(smraw + (3*64*PA)*4);         // 64 x PV (tf32)
    float*    msh  = (float*)(Vs + 64*PV);
    float*    lsh  = msh + 64;
    float*    alsh = lsh + 64;
    float*    madd = alsh + 64;

    const int tid  = threadIdx.x;
    const int wid  = tid >> 5;
    const int lane = tid & 31;
    const int g    = lane >> 2;
    const int tg   = lane & 3;
    const int wr   = wid >> 1;          // 0..3
    const int wc   = wid & 1;           // 0..1
    const int rb   = wr * 16;

    const int bh = blockIdx.x;          // 0..31
    const int b  = bh >> 4;
    const int h  = bh & 15;
    const int q0 = blockIdx.y * 64;

    const float* Qh = Q + (size_t)bh * QLEN * HD;
    const float* Kh = K + (size_t)bh * QLEN * HD;
    const float* Vh = V + (size_t)bh * QLEN * HD;
    const float* mb = mask + (size_t)b * QLEN;

    // stage Q (tf32)
    #pragma unroll
    for (int i = 0; i < 16; i++) {
        int idx = tid + i * 256;
        int r = idx >> 6, c = idx & 63;
        Qs[r * PA + c] = f2tf32(Qh[(size_t)(q0 + r) * HD + c]);
    }
    if (tid < 64) { msh[tid] = -1e30f; lsh[tid] = 0.0f; }

    float o[4][4];
    #pragma unroll
    for (int nt = 0; nt < 4; nt++)
        #pragma unroll
        for (int i = 0; i < 4; i++) o[nt][i] = 0.0f;

    for (int t = 0; t < QLEN / 64; t++) {
        const int kk0 = t * 64;
        __syncthreads();     // prev PV done before restaging

        // K, V: load float4, convert to tf32, store
        #pragma unroll
        for (int i = 0; i < 4; i++) {
            int idx = tid + i * 256;
            int r = idx >> 4, c4 = (idx & 15) * 4;
            float4 kv = *(const float4*)(Kh + (size_t)(kk0 + r) * HD + c4);
            uint4 kt4;
            kt4.x = f2tf32(kv.x); kt4.y = f2tf32(kv.y);
            kt4.z = f2tf32(kv.z); kt4.w = f2tf32(kv.w);
            *(uint4*)(&Ks[r * PA + c4]) = kt4;
            float4 vv = *(const float4*)(Vh + (size_t)(kk0 + r) * HD + c4);
            uint4 vt4;
            vt4.x = f2tf32(vv.x); vt4.y = f2tf32(vv.y);
            vt4.z = f2tf32(vv.z); vt4.w = f2tf32(vv.w);
            *(uint4*)(&Vs[r * PV + c4]) = vt4;
        }
        if (tid < 64) madd[tid] = -1e30f * (1.0f - mb[kk0 + tid]);
        __syncthreads();

        // S = Q @ K^T (this warp: rows rb..rb+15, keys wc*32..+31)
        float sacc[4][4];
        #pragma unroll
        for (int nt = 0; nt < 4; nt++)
            #pragma unroll
            for (int i = 0; i < 4; i++) sacc[nt][i] = 0.0f;

        #pragma unroll
        for (int ks = 0; ks < 8; ks++) {
            const int k = ks * 8;
            uint32_t a0 = Qs[(rb + g    ) * PA + k + tg    ];
            uint32_t a1 = Qs[(rb + g + 8) * PA + k + tg    ];
            uint32_t a2 = Qs[(rb + g    ) * PA + k + tg + 4];
            uint32_t a3 = Qs[(rb + g + 8) * PA + k + tg + 4];
            #pragma unroll
            for (int nt = 0; nt < 4; nt++) {
                const int n0 = wc * 32 + nt * 8 + g;
                uint32_t b0 = Ks[n0 * PA + k + tg    ];
                uint32_t b1 = Ks[n0 * PA + k + tg + 4];
                mma_tf32(sacc[nt], a0, a1, a2, a3, b0, b1);
            }
        }
        #pragma unroll
        for (int nt = 0; nt < 4; nt++) {
            const int col = wc * 32 + nt * 8 + tg * 2;
            Ssh[(rb + g    ) * PA + col    ] = sacc[nt][0] + madd[col];
            Ssh[(rb + g    ) * PA + col + 1] = sacc[nt][1] + madd[col + 1];
            Ssh[(rb + g + 8) * PA + col    ] = sacc[nt][2] + madd[col];
            Ssh[(rb + g + 8) * PA + col + 1] = sacc[nt][3] + madd[col + 1];
        }
        __syncthreads();

        // online softmax: 4 threads per row; write P as tf32 bits
        {
            const int row = tid >> 2;
            const int sg  = tid & 3;
            float tmax = -1e30f;
            #pragma unroll
            for (int c = 0; c < 16; c++)
                tmax = fmaxf(tmax, Ssh[row * PA + sg + c * 4]);
            tmax = fmaxf(tmax, __shfl_xor_sync(0xffffffffu, tmax, 1));
            tmax = fmaxf(tmax, __shfl_xor_sync(0xffffffffu, tmax, 2));
            const float m_old = msh[row];
            const float m_new = fmaxf(m_old, tmax);
            float sum = 0.0f;
            #pragma unroll
            for (int c = 0; c < 16; c++) {
                float p = __expf(Ssh[row * PA + sg + c * 4] - m_new);
                Ssh[row * PA + sg + c * 4] = __uint_as_float(f2tf32(p));
                sum += p;
            }
            sum += __shfl_xor_sync(0xffffffffu, sum, 1);
            sum += __shfl_xor_sync(0xffffffffu, sum, 2);
            if (sg == 0) {
                const float alpha = __expf(m_old - m_new);
                msh[row]  = m_new;
                lsh[row]  = lsh[row] * alpha + sum;
                alsh[row] = alpha;
            }
        }
        __syncthreads();

        // rescale O, then O += P @ V
        {
            const float a_lo = alsh[rb + g];
            const float a_hi = alsh[rb + g + 8];
            #pragma unroll
            for (int nt = 0; nt < 4; nt++) {
                o[nt][0] *= a_lo; o[nt][1] *= a_lo;
                o[nt][2] *= a_hi; o[nt][3] *= a_hi;
            }
        }
        #pragma unroll
        for (int ks = 0; ks < 8; ks++) {
            const int k = ks * 8;
            uint32_t a0 = __float_as_uint(Ssh[(rb + g    ) * PA + k + tg    ]);
            uint32_t a1 = __float_as_uint(Ssh[(rb + g + 8) * PA + k + tg    ]);
            uint32_t a2 = __float_as_uint(Ssh[(rb + g    ) * PA + k + tg + 4]);
            uint32_t a3 = __float_as_uint(Ssh[(rb + g + 8) * PA + k + tg + 4]);
            #pragma unroll
            for (int nt = 0; nt < 4; nt++) {
                const int d0 = wc * 32 + nt * 8 + g;
                uint32_t b0 = Vs[(k + tg    ) * PV + d0];
                uint32_t b1 = Vs[(k + tg + 4) * PV + d0];
                mma_tf32(o[nt], a0, a1, a2, a3, b0, b1);
            }
        }
    }

    // write context [b, q, h*HD + d]
    const float inv_lo = 1.0f / lsh[rb + g];
    const float inv_hi = 1.0f / lsh[rb + g + 8];
    #pragma unroll
    for (int nt = 0; nt < 4; nt++) {
        const int d = h * HD + wc * 32 + nt * 8 + tg * 2;
        const int m0 = q0 + rb + g;
        float2 v0; v0.x = o[nt][0] * inv_lo; v0.y = o[nt][1] * inv_lo;
        *(float2*)(&ctx[((size_t)(b * QLEN + m0)) * DIM + d]) = v0;
        float2 v1; v1.x = o[nt][2] * inv_hi; v1.y = o[nt][3] * inv_hi;
        *(float2*)(&ctx[((size_t)(b * QLEN + m0 + 8)) * DIM + d]) = v1;
    }
}

// ---------------------------------------------------------------------------
extern "C" void kernel_launch(void* const* d_in, const int* in_sizes, int n_in,
                              void* d_out, int out_size)
{
    const float* x    = (const float*)d_in[0];
    const float* mask = (const float*)d_in[1];
    const float* Wq   = (const float*)d_in[2];
    const float* bq   = (const float*)d_in[3];
    const float* Wk   = (const float*)d_in[4];
    const float* bk   = (const float*)d_in[5];
    const float* Wv   = (const float*)d_in[6];
    const float* bv   = (const float*)d_in[7];
    const float* Wo   = (const float*)d_in[8];
    const float* bo   = (const float*)d_in[9];
    float* out = (float*)d_out;

    float *Qp, *Kp, *Vp, *Cp, *WqT, *WkT, *WvT, *WoT;
    cudaGetSymbolAddress((void**)&Qp, g_Q);
    cudaGetSymbolAddress((void**)&Kp, g_K);
    cudaGetSymbolAddress((void**)&Vp, g_V);
    cudaGetSymbolAddress((void**)&Cp, g_C);
    cudaGetSymbolAddress((void**)&WqT, g_WqT);
    cudaGetSymbolAddress((void**)&WkT, g_WkT);
    cudaGetSymbolAddress((void**)&WvT, g_WvT);
    cudaGetSymbolAddress((void**)&WoT, g_WoT);

    const dim3 tg(32, 32), tb(32, 8);
    transpose1024<<<tg, tb>>>(Wq, WqT);
    transpose1024<<<tg, tb>>>(Wk, WkT);
    transpose1024<<<tg, tb>>>(Wv, WvT);
    transpose1024<<<tg, tb>>>(Wo, WoT);

    const dim3 gg(DIM / 128, MTOT / 128);
    const float qscale = 1.0f / sqrtf((float)HD);

    gemm_mma<1><<<gg, 256>>>(x, WqT, bq, Qp, qscale);
    gemm_mma<1><<<gg, 256>>>(x, WkT, bk, Kp, 1.0f);
    gemm_mma<1><<<gg, 256>>>(x, WvT, bv, Vp, 1.0f);

    cudaFuncSetAttribute(attn_mma, cudaFuncAttributeMaxDynamicSharedMemorySize, ATTN_SMEM);
    attn_mma<<<dim3(BSZ * NH, QLEN / 64), 256, ATTN_SMEM>>>(Qp, Kp, Vp, mask, Cp);

    gemm_mma<0><<<gg, 256>>>(Cp, WoT, bo, out, 1.0f);
}

// round 8
// speedup vs baseline: 3.8129x; 1.0589x over previous
#include <cuda_runtime.h>
#include <cstdint>
#include <math.h>

// Problem dims
#define BSZ   2
#define QLEN  2048
#define DIM   1024
#define NH    16
#define HD    64
#define MTOT  (BSZ*QLEN)   // 4096

// Scratch (device globals: allocation-free). Q/K/V/C/W*T/Xt hold tf32 bit patterns.
__device__ uint32_t g_Q[BSZ*NH*QLEN*HD];
__device__ uint32_t g_K[BSZ*NH*QLEN*HD];
__device__ uint32_t g_V[BSZ*NH*QLEN*HD];
__device__ uint32_t g_C[MTOT*DIM];
__device__ uint32_t g_Xt[MTOT*DIM];
__device__ uint32_t g_WqT[DIM*DIM];
__device__ uint32_t g_WkT[DIM*DIM];
__device__ uint32_t g_WvT[DIM*DIM];
__device__ uint32_t g_WoT[DIM*DIM];

__device__ __forceinline__ uint32_t smem_u32(const void* p) {
    uint32_t a;
    asm("{ .reg .u64 t; cvta.to.shared.u64 t, %1; cvt.u32.u64 %0, t; }" : "=r"(a) : "l"(p));
    return a;
}
__device__ __forceinline__ void cp16(uint32_t saddr, const void* gaddr) {
    asm volatile("cp.async.cg.shared.global [%0], [%1], 16;" :: "r"(saddr), "l"(gaddr));
}
__device__ __forceinline__ void cp_commit() { asm volatile("cp.async.commit_group;"); }
template<int N>
__device__ __forceinline__ void cp_wait() { asm volatile("cp.async.wait_group %0;" :: "n"(N)); }

__device__ __forceinline__ uint32_t f2tf32(float f) {
    uint32_t u;
    asm("cvt.rna.tf32.f32 %0, %1;" : "=r"(u) : "f"(f));
    return u;
}
__device__ __forceinline__ void mma_tf32(float c[4],
    uint32_t a0, uint32_t a1, uint32_t a2, uint32_t a3, uint32_t b0, uint32_t b1)
{
    asm volatile(
        "mma.sync.aligned.m16n8k8.row.col.f32.tf32.tf32.f32 "
        "{%0,%1,%2,%3}, {%4,%5,%6,%7}, {%8,%9}, {%0,%1,%2,%3};"
        : "+f"(c[0]), "+f"(c[1]), "+f"(c[2]), "+f"(c[3])
        : "r"(a0), "r"(a1), "r"(a2), "r"(a3), "r"(b0), "r"(b1));
}

// ---------------------------------------------------------------------------
// elementwise fp32 -> tf32 bits
// ---------------------------------------------------------------------------
__global__ void to_tf32(const float* __restrict__ in, uint32_t* __restrict__ out)
{
    int idx = (blockIdx.x * 256 + threadIdx.x) * 4;
    float4 v = *(const float4*)(in + idx);
    uint4 u;
    u.x = f2tf32(v.x); u.y = f2tf32(v.y); u.z = f2tf32(v.z); u.w = f2tf32(v.w);
    *(uint4*)(out + idx) = u;
}

// ---------------------------------------------------------------------------
// 32x32 tiled transpose, emits tf32 bits: out[n*1024+k] = tf32(in[k*1024+n])
// ---------------------------------------------------------------------------
__global__ void transpose1024(const float* __restrict__ in, uint32_t* __restrict__ out)
{
    __shared__ float tile[32][33];
    int x = blockIdx.x * 32 + threadIdx.x;
    int y = blockIdx.y * 32 + threadIdx.y;
    #pragma unroll
    for (int i = 0; i < 32; i += 8)
        tile[threadIdx.y + i][threadIdx.x] = in[(size_t)(y + i) * DIM + x];
    __syncthreads();
    int x2 = blockIdx.y * 32 + threadIdx.x;
    int y2 = blockIdx.x * 32 + threadIdx.y;
    #pragma unroll
    for (int i = 0; i < 32; i += 8)
        out[(size_t)(y2 + i) * DIM + x2] = f2tf32(tile[threadIdx.x][threadIdx.y + i]);
}

// ---------------------------------------------------------------------------
// tf32 mma.sync GEMM, operands pre-converted tf32 bits. Pure LDS+MMA mainloop.
// MODE 0: fp32 row-major out (final output). MODE 1: tf32-bits head-split out.
// ---------------------------------------------------------------------------
#define BM 128
#define BN 128
#define BK 16
#define PADK 20
#define KTILES (DIM/BK)

template<int MODE>
__global__ void __launch_bounds__(256) gemm_mma(
    const uint32_t* __restrict__ A, const uint32_t* __restrict__ Wt,
    const float* __restrict__ bias, void* __restrict__ outp, float scale)
{
    __shared__ uint32_t As[2][BM * PADK];
    __shared__ uint32_t Bs[2][BN * PADK];
    __shared__ float s_bias[BN];

    const int tid  = threadIdx.x;
    const int wid  = tid >> 5;
    const int lane = tid & 31;
    const int g    = lane >> 2;
    const int tg   = lane & 3;
    const int wr   = wid >> 2;
    const int wc   = wid & 3;
    const int br   = blockIdx.y * BM;
    const int bc   = blockIdx.x * BN;

    if (tid < BN) s_bias[tid] = bias[bc + tid];

    uint32_t aAddr[2], bAddr[2];
    const uint32_t* aPtr[2];
    const uint32_t* bPtr[2];
    const uint32_t aBase = smem_u32(As);
    const uint32_t bBase = smem_u32(Bs);
    #pragma unroll
    for (int i = 0; i < 2; i++) {
        int idx = i * 256 + tid;
        int row = idx >> 2;
        int k4  = (idx & 3) * 4;
        aAddr[i] = aBase + (uint32_t)(row * PADK + k4) * 4u;
        bAddr[i] = bBase + (uint32_t)(row * PADK + k4) * 4u;
        aPtr[i]  = A  + (size_t)(br + row) * DIM + k4;
        bPtr[i]  = Wt + (size_t)(bc + row) * DIM + k4;
    }
    const uint32_t stageA = (uint32_t)(BM * PADK) * 4u;
    const uint32_t stageB = (uint32_t)(BN * PADK) * 4u;

    float acc[4][4][4];
    #pragma unroll
    for (int mt = 0; mt < 4; mt++)
        #pragma unroll
        for (int nt = 0; nt < 4; nt++)
            #pragma unroll
            for (int i = 0; i < 4; i++) acc[mt][nt][i] = 0.0f;

    #pragma unroll
    for (int i = 0; i < 2; i++) { cp16(aAddr[i], aPtr[i]); cp16(bAddr[i], bPtr[i]); }
    cp_commit();

    for (int kt = 0; kt < KTILES; kt++) {
        const int buf = kt & 1;
        if (kt + 1 < KTILES) {
            const int nb = (kt + 1) & 1;
            const int k0 = (kt + 1) * BK;
            #pragma unroll
            for (int i = 0; i < 2; i++) {
                cp16(aAddr[i] + nb * stageA, aPtr[i] + k0);
                cp16(bAddr[i] + nb * stageB, bPtr[i] + k0);
            }
            cp_commit();
            cp_wait<1>();
        } else {
            cp_wait<0>();
        }
        __syncthreads();

        const uint32_t* Ab = As[buf];
        const uint32_t* Bb = Bs[buf];
        #pragma unroll
        for (int ks = 0; ks < BK; ks += 8) {
            uint32_t af[4][4];
            #pragma unroll
            for (int mt = 0; mt < 4; mt++) {
                const int r0 = wr * 64 + mt * 16 + g;
                af[mt][0] = Ab[(r0    ) * PADK + ks + tg    ];
                af[mt][1] = Ab[(r0 + 8) * PADK + ks + tg    ];
                af[mt][2] = Ab[(r0    ) * PADK + ks + tg + 4];
                af[mt][3] = Ab[(r0 + 8) * PADK + ks + tg + 4];
            }
            uint32_t bf[4][2];
            #pragma unroll
            for (int nt = 0; nt < 4; nt++) {
                const int n0 = wc * 32 + nt * 8 + g;
                bf[nt][0] = Bb[n0 * PADK + ks + tg    ];
                bf[nt][1] = Bb[n0 * PADK + ks + tg + 4];
            }
            #pragma unroll
            for (int mt = 0; mt < 4; mt++)
                #pragma unroll
                for (int nt = 0; nt < 4; nt++)
                    mma_tf32(acc[mt][nt], af[mt][0], af[mt][1], af[mt][2], af[mt][3],
                             bf[nt][0], bf[nt][1]);
        }
        __syncthreads();
    }

    #pragma unroll
    for (int mt = 0; mt < 4; mt++) {
        #pragma unroll
        for (int nt = 0; nt < 4; nt++) {
            const int nl = wc * 32 + nt * 8 + tg * 2;
            const int n  = bc + nl;
            const float b0 = s_bias[nl], b1 = s_bias[nl + 1];
            #pragma unroll
            for (int half = 0; half < 2; half++) {
                const int m = br + wr * 64 + mt * 16 + g + half * 8;
                float vx = (acc[mt][nt][half * 2 + 0] + b0) * scale;
                float vy = (acc[mt][nt][half * 2 + 1] + b1) * scale;
                if (MODE == 0) {
                    float2 v; v.x = vx; v.y = vy;
                    *(float2*)((float*)outp + (size_t)m * DIM + n) = v;
                } else {
                    uint2 u; u.x = f2tf32(vx); u.y = f2tf32(vy);
                    const int bb = m >> 11, q = m & 2047, h = n >> 6, d = n & 63;
                    *(uint2*)((uint32_t*)outp + (((size_t)bb * NH + h) * QLEN + q) * HD + d) = u;
                }
            }
        }
    }
}

// ---------------------------------------------------------------------------
// Tensor-core flash attention, tf32 operands at rest.
// Q tile 128 x HD; K tile 64. 8 warps in 4x2; warp tile 32x32 (2 LDS/MMA).
// K/V staged via cp.async (bit copies). ctx written as tf32 bits.
// ---------------------------------------------------------------------------
#define PA 68
#define PV 72
#define ATTN_SMEM ((128*PA*2 + 64*PA + 64*PV + 3*128 + 64) * 4)

__global__ void __launch_bounds__(256) attn_mma(
    const uint32_t* __restrict__ Q, const uint32_t* __restrict__ K,
    const uint32_t* __restrict__ V, const float* __restrict__ mask,
    uint32_t* __restrict__ ctx)
{
    extern __shared__ unsigned char smraw[];
    uint32_t* Qs  = (uint32_t*)smraw;                          // 128 x PA
    float*    Ssh = (float*)(smraw + (128*PA)*4);              // 128 x PA
    uint32_t* Ks  = (uint32_t*)(smraw + (2*128*PA)*4);         // 64 x PA
    uint32_t* Vs  = (uint32_t*)(smraw + (2*128*PA + 64*PA)*4); // 64 x PV
    float*    msh  = (float*)(Vs + 64*PV);                     // 128
    float*    lsh  = msh + 128;                                // 128
    float*    alsh = lsh + 128;                                // 128
    float*    madd = alsh + 128;                               // 64

    const int tid  = threadIdx.x;
    const int wid  = tid >> 5;
    const int lane = tid & 31;
    const int g    = lane >> 2;
    const int tg   = lane & 3;
    const int wr   = wid >> 1;          // 0..3 -> 32-row slab
    const int wc   = wid & 1;           // 0..1 -> 32-col slab
    const int rb   = wr * 32;

    const int bh = blockIdx.x;          // 0..31
    const int b  = bh >> 4;
    const int h  = bh & 15;
    const int q0 = blockIdx.y * 128;

    const uint32_t* Qh = Q + (size_t)bh * QLEN * HD;
    const uint32_t* Kh = K + (size_t)bh * QLEN * HD;
    const uint32_t* Vh = V + (size_t)bh * QLEN * HD;
    const float* mb = mask + (size_t)b * QLEN;

    const uint32_t ksBase = smem_u32(Ks);
    const uint32_t vsBase = smem_u32(Vs);

    // stage Q (bit copy): 128x64 = 2048 uint4
    #pragma unroll
    for (int i = 0; i < 8; i++) {
        int idx = tid + i * 256;            // uint4 index
        int r = idx >> 4, c4 = (idx & 15) * 4;
        *(uint4*)(&Qs[r * PA + c4]) = *(const uint4*)(Qh + (size_t)(q0 + r) * HD + c4);
    }
    if (tid < 128) { msh[tid] = -1e30f; lsh[tid] = 0.0f; }

    float o[2][4][4];
    #pragma unroll
    for (int mt = 0; mt < 2; mt++)
        #pragma unroll
        for (int nt = 0; nt < 4; nt++)
            #pragma unroll
            for (int i = 0; i < 4; i++) o[mt][nt][i] = 0.0f;

    for (int t = 0; t < QLEN / 64; t++) {
        const int kk0 = t * 64;
        __syncthreads();     // prev PV done before restaging

        // K, V via cp.async (4096 elems each -> 4 cp16 per thread each)
        #pragma unroll
        for (int i = 0; i < 4; i++) {
            int idx = tid + i * 256;
            int r = idx >> 4, c4 = (idx & 15) * 4;
            cp16(ksBase + (uint32_t)(r * PA + c4) * 4u, Kh + (size_t)(kk0 + r) * HD + c4);
            cp16(vsBase + (uint32_t)(r * PV + c4) * 4u, Vh + (size_t)(kk0 + r) * HD + c4);
        }
        cp_commit();
        if (tid < 64) madd[tid] = -1e30f * (1.0f - mb[kk0 + tid]);
        cp_wait<0>();
        __syncthreads();

        // S = Q @ K^T : warp rows rb..rb+31, keys wc*32..+31
        float sacc[2][4][4];
        #pragma unroll
        for (int mt = 0; mt < 2; mt++)
            #pragma unroll
            for (int nt = 0; nt < 4; nt++)
                #pragma unroll
                for (int i = 0; i < 4; i++) sacc[mt][nt][i] = 0.0f;

        #pragma unroll
        for (int ks = 0; ks < 8; ks++) {
            const int k = ks * 8;
            uint32_t af[2][4];
            #pragma unroll
            for (int mt = 0; mt < 2; mt++) {
                const int r0 = rb + mt * 16 + g;
                af[mt][0] = Qs[(r0    ) * PA + k + tg    ];
                af[mt][1] = Qs[(r0 + 8) * PA + k + tg    ];
                af[mt][2] = Qs[(r0    ) * PA + k + tg + 4];
                af[mt][3] = Qs[(r0 + 8) * PA + k + tg + 4];
            }
            #pragma unroll
            for (int nt = 0; nt < 4; nt++) {
                const int n0 = wc * 32 + nt * 8 + g;
                uint32_t b0 = Ks[n0 * PA + k + tg    ];
                uint32_t b1 = Ks[n0 * PA + k + tg + 4];
                #pragma unroll
                for (int mt = 0; mt < 2; mt++)
                    mma_tf32(sacc[mt][nt], af[mt][0], af[mt][1], af[mt][2], af[mt][3], b0, b1);
            }
        }
        #pragma unroll
        for (int mt = 0; mt < 2; mt++)
            #pragma unroll
            for (int nt = 0; nt < 4; nt++) {
                const int col = wc * 32 + nt * 8 + tg * 2;
                const int r0  = rb + mt * 16 + g;
                Ssh[(r0    ) * PA + col    ] = sacc[mt][nt][0] + madd[col];
                Ssh[(r0    ) * PA + col + 1] = sacc[mt][nt][1] + madd[col + 1];
                Ssh[(r0 + 8) * PA + col    ] = sacc[mt][nt][2] + madd[col];
                Ssh[(r0 + 8) * PA + col + 1] = sacc[mt][nt][3] + madd[col + 1];
            }
        __syncthreads();

        // online softmax: 2 threads per row (128 rows); write P as tf32 bits
        {
            const int row = tid >> 1;
            const int sg  = tid & 1;
            float tmax = -1e30f;
            #pragma unroll
            for (int c = 0; c < 32; c++)
                tmax = fmaxf(tmax, Ssh[row * PA + sg + c * 2]);
            tmax = fmaxf(tmax, __shfl_xor_sync(0xffffffffu, tmax, 1));
            const float m_old = msh[row];
            const float m_new = fmaxf(m_old, tmax);
            float sum = 0.0f;
            #pragma unroll
            for (int c = 0; c < 32; c++) {
                float p = __expf(Ssh[row * PA + sg + c * 2] - m_new);
                Ssh[row * PA + sg + c * 2] = __uint_as_float(f2tf32(p));
                sum += p;
            }
            sum += __shfl_xor_sync(0xffffffffu, sum, 1);
            if (sg == 0) {
                const float alpha = __expf(m_old - m_new);
                msh[row]  = m_new;
                lsh[row]  = lsh[row] * alpha + sum;
                alsh[row] = alpha;
            }
        }
        __syncthreads();

        // rescale O, then O += P @ V
        #pragma unroll
        for (int mt = 0; mt < 2; mt++) {
            const float a_lo = alsh[rb + mt * 16 + g];
            const float a_hi = alsh[rb + mt * 16 + g + 8];
            #pragma unroll
            for (int nt = 0; nt < 4; nt++) {
                o[mt][nt][0] *= a_lo; o[mt][nt][1] *= a_lo;
                o[mt][nt][2] *= a_hi; o[mt][nt][3] *= a_hi;
            }
        }
        #pragma unroll
        for (int ks = 0; ks < 8; ks++) {
            const int k = ks * 8;
            uint32_t af[2][4];
            #pragma unroll
            for (int mt = 0; mt < 2; mt++) {
                const int r0 = rb + mt * 16 + g;
                af[mt][0] = __float_as_uint(Ssh[(r0    ) * PA + k + tg    ]);
                af[mt][1] = __float_as_uint(Ssh[(r0 + 8) * PA + k + tg    ]);
                af[mt][2] = __float_as_uint(Ssh[(r0    ) * PA + k + tg + 4]);
                af[mt][3] = __float_as_uint(Ssh[(r0 + 8) * PA + k + tg + 4]);
            }
            #pragma unroll
            for (int nt = 0; nt < 4; nt++) {
                const int d0 = wc * 32 + nt * 8 + g;
                uint32_t b0 = Vs[(k + tg    ) * PV + d0];
                uint32_t b1 = Vs[(k + tg + 4) * PV + d0];
                #pragma unroll
                for (int mt = 0; mt < 2; mt++)
                    mma_tf32(o[mt][nt], af[mt][0], af[mt][1], af[mt][2], af[mt][3], b0, b1);
            }
        }
    }

    // write context [b, q, h*HD + d] as tf32 bits
    #pragma unroll
    for (int mt = 0; mt < 2; mt++) {
        const int r0 = rb + mt * 16 + g;
        const float inv_lo = 1.0f / lsh[r0];
        const float inv_hi = 1.0f / lsh[r0 + 8];
        #pragma unroll
        for (int nt = 0; nt < 4; nt++) {
            const int d = h * HD + wc * 32 + nt * 8 + tg * 2;
            const int m0 = q0 + r0;
            uint2 u0; u0.x = f2tf32(o[mt][nt][0] * inv_lo); u0.y = f2tf32(o[mt][nt][1] * inv_lo);
            *(uint2*)(&ctx[((size_t)(b * QLEN + m0)) * DIM + d]) = u0;
            uint2 u1; u1.x = f2tf32(o[mt][nt][2] * inv_hi); u1.y = f2tf32(o[mt][nt][3] * inv_hi);
            *(uint2*)(&ctx[((size_t)(b * QLEN + m0 + 8)) * DIM + d]) = u1;
        }
    }
}

// ---------------------------------------------------------------------------
extern "C" void kernel_launch(void* const* d_in, const int* in_sizes, int n_in,
                              void* d_out, int out_size)
{
    const float* x    = (const float*)d_in[0];
    const float* mask = (const float*)d_in[1];
    const float* Wq   = (const float*)d_in[2];
    const float* bq   = (const float*)d_in[3];
    const float* Wk   = (const float*)d_in[4];
    const float* bk   = (const float*)d_in[5];
    const float* Wv   = (const float*)d_in[6];
    const float* bv   = (const float*)d_in[7];
    const float* Wo   = (const float*)d_in[8];
    const float* bo   = (const float*)d_in[9];
    float* out = (float*)d_out;

    uint32_t *Qp, *Kp, *Vp, *Cp, *Xt, *WqT, *WkT, *WvT, *WoT;
    cudaGetSymbolAddress((void**)&Qp, g_Q);
    cudaGetSymbolAddress((void**)&Kp, g_K);
    cudaGetSymbolAddress((void**)&Vp, g_V);
    cudaGetSymbolAddress((void**)&Cp, g_C);
    cudaGetSymbolAddress((void**)&Xt, g_Xt);
    cudaGetSymbolAddress((void**)&WqT, g_WqT);
    cudaGetSymbolAddress((void**)&WkT, g_WkT);
    cudaGetSymbolAddress((void**)&WvT, g_WvT);
    cudaGetSymbolAddress((void**)&WoT, g_WoT);

    to_tf32<<<MTOT * DIM / 1024, 256>>>(x, Xt);
    const dim3 tg(32, 32), tb(32, 8);
    transpose1024<<<tg, tb>>>(Wq, WqT);
    transpose1024<<<tg, tb>>>(Wk, WkT);
    transpose1024<<<tg, tb>>>(Wv, WvT);
    transpose1024<<<tg, tb>>>(Wo, WoT);

    const dim3 gg(DIM / 128, MTOT / 128);
    const float qscale = 1.0f / sqrtf((float)HD);

    gemm_mma<1><<<gg, 256>>>(Xt, WqT, bq, Qp, qscale);
    gemm_mma<1><<<gg, 256>>>(Xt, WkT, bk, Kp, 1.0f);
    gemm_mma<1><<<gg, 256>>>(Xt, WvT, bv, Vp, 1.0f);

    cudaFuncSetAttribute(attn_mma, cudaFuncAttributeMaxDynamicSharedMemorySize, ATTN_SMEM);
    attn_mma<<<dim3(BSZ * NH, QLEN / 128), 256, ATTN_SMEM>>>(Qp, Kp, Vp, mask, Cp);

    gemm_mma<0><<<gg, 256>>>(Cp, WoT, bo, out, 1.0f);
}

// round 10
// speedup vs baseline: 4.0270x; 1.0562x over previous
#include <cuda_runtime.h>
#include <cstdint>
#include <math.h>

// Problem dims
#define BSZ   2
#define QLEN  2048
#define DIM   1024
#define NH    16
#define HD    64
#define MTOT  (BSZ*QLEN)   // 4096

// Scratch (device globals). Q/K/V/C/Xt/W*T hold tf32 bit patterns.
__device__ uint32_t g_Q[BSZ*NH*QLEN*HD];
__device__ uint32_t g_K[BSZ*NH*QLEN*HD];
__device__ uint32_t g_V[BSZ*NH*QLEN*HD];
__device__ uint32_t g_C[MTOT*DIM];
__device__ uint32_t g_Xt[MTOT*DIM];
__device__ uint32_t g_WqkvT[3*DIM*DIM];   // rows 0..1023 Wq^T, 1024.. Wk^T, 2048.. Wv^T
__device__ uint32_t g_WoT[DIM*DIM];

__device__ __forceinline__ uint32_t smem_u32(const void* p) {
    uint32_t a;
    asm("{ .reg .u64 t; cvta.to.shared.u64 t, %1; cvt.u32.u64 %0, t; }" : "=r"(a) : "l"(p));
    return a;
}
__device__ __forceinline__ void cp16(uint32_t saddr, const void* gaddr) {
    asm volatile("cp.async.cg.shared.global [%0], [%1], 16;" :: "r"(saddr), "l"(gaddr));
}
__device__ __forceinline__ void cp_commit() { asm volatile("cp.async.commit_group;"); }
template<int N>
__device__ __forceinline__ void cp_wait() { asm volatile("cp.async.wait_group %0;" :: "n"(N)); }

__device__ __forceinline__ uint32_t f2tf32(float f) {
    uint32_t u;
    asm("cvt.rna.tf32.f32 %0, %1;" : "=r"(u) : "f"(f));
    return u;
}
__device__ __forceinline__ void mma_tf32(float c[4],
    uint32_t a0, uint32_t a1, uint32_t a2, uint32_t a3, uint32_t b0, uint32_t b1)
{
    asm volatile(
        "mma.sync.aligned.m16n8k8.row.col.f32.tf32.tf32.f32 "
        "{%0,%1,%2,%3}, {%4,%5,%6,%7}, {%8,%9}, {%0,%1,%2,%3};"
        : "+f"(c[0]), "+f"(c[1]), "+f"(c[2]), "+f"(c[3])
        : "r"(a0), "r"(a1), "r"(a2), "r"(a3), "r"(b0), "r"(b1));
}

// ---------------------------------------------------------------------------
// elementwise fp32 -> tf32 bits
// ---------------------------------------------------------------------------
__global__ void to_tf32(const float* __restrict__ in, uint32_t* __restrict__ out)
{
    int idx = (blockIdx.x * 256 + threadIdx.x) * 4;
    float4 v = *(const float4*)(in + idx);
    uint4 u;
    u.x = f2tf32(v.x); u.y = f2tf32(v.y); u.z = f2tf32(v.z); u.w = f2tf32(v.w);
    *(uint4*)(out + idx) = u;
}

// ---------------------------------------------------------------------------
// Batched 32x32 transpose of 4 weight matrices, emits tf32 bits.
// z = 0,1,2 -> Wq,Wk,Wv into g_WqkvT + z*DIM*DIM; z = 3 -> Wo into g_WoT.
// ---------------------------------------------------------------------------
__global__ void transpose_w(const float* __restrict__ w0, const float* __restrict__ w1,
                            const float* __restrict__ w2, const float* __restrict__ w3,
                            uint32_t* __restrict__ qkvT, uint32_t* __restrict__ woT)
{
    __shared__ float tile[32][33];
    const int z = blockIdx.z;
    const float* in = (z == 0) ? w0 : (z == 1) ? w1 : (z == 2) ? w2 : w3;
    uint32_t* out = (z < 3) ? (qkvT + (size_t)z * DIM * DIM) : woT;

    int x = blockIdx.x * 32 + threadIdx.x;
    int y = blockIdx.y * 32 + threadIdx.y;
    #pragma unroll
    for (int i = 0; i < 32; i += 8)
        tile[threadIdx.y + i][threadIdx.x] = in[(size_t)(y + i) * DIM + x];
    __syncthreads();
    int x2 = blockIdx.y * 32 + threadIdx.x;
    int y2 = blockIdx.x * 32 + threadIdx.y;
    #pragma unroll
    for (int i = 0; i < 32; i += 8)
        out[(size_t)(y2 + i) * DIM + x2] = f2tf32(tile[threadIdx.x][threadIdx.y + i]);
}

// ---------------------------------------------------------------------------
// tf32 mma.sync GEMM core. BK=32, dynamic smem, pure LDS+MMA mainloop.
// MODE 0: Wo path  -> fp32 row-major out, single bias, scale 1.
// MODE 1: QKV path -> Wt is [3072,1024]; epilogue routes by n>>10 to
//                     Q (x qscale) / K / V head-split buffers, bias per segment.
// ---------------------------------------------------------------------------
#define BM 128
#define BN 128
#define BK 32
#define PADK 36
#define GEMM_SMEM (2 * 2 * BM * PADK * 4 + BN * 4)

template<int MODE>
__global__ void __launch_bounds__(256) gemm_mma(
    const uint32_t* __restrict__ A, const uint32_t* __restrict__ Wt,
    const float* __restrict__ bias0, const float* __restrict__ bias1,
    const float* __restrict__ bias2,
    uint32_t* __restrict__ q_out, uint32_t* __restrict__ k_out,
    uint32_t* __restrict__ v_out, float* __restrict__ f_out, float qscale)
{
    extern __shared__ unsigned char dynsm[];
    uint32_t* As = (uint32_t*)dynsm;                          // 2 x BM x PADK
    uint32_t* Bs = As + 2 * BM * PADK;                        // 2 x BN x PADK
    float* s_bias = (float*)(Bs + 2 * BN * PADK);             // BN

    const int tid  = threadIdx.x;
    const int wid  = tid >> 5;
    const int lane = tid & 31;
    const int g    = lane >> 2;
    const int tg   = lane & 3;
    const int wr   = wid >> 2;
    const int wc   = wid & 3;
    const int br   = blockIdx.y * BM;
    const int bc   = blockIdx.x * BN;
    const int seg  = (MODE == 1) ? (bc >> 10) : 0;            // 0=Q,1=K,2=V

    if (tid < BN) {
        const float* bp = (MODE == 0) ? bias0
                         : (seg == 0) ? bias0 : (seg == 1) ? bias1 : bias2;
        s_bias[tid] = bp[(MODE == 1 ? (bc & 1023) : bc) + tid];
    }

    // cp.async mapping: 128x32 per operand per stage = 1024 uint4; 4 per thread.
    uint32_t aAddr[4], bAddr[4];
    const uint32_t* aPtr[4];
    const uint32_t* bPtr[4];
    const uint32_t aBase = smem_u32(As);
    const uint32_t bBase = smem_u32(Bs);
    #pragma unroll
    for (int i = 0; i < 4; i++) {
        int u = i * 256 + tid;
        int row = u >> 3;
        int k4  = (u & 7) * 4;
        aAddr[i] = aBase + (uint32_t)(row * PADK + k4) * 4u;
        bAddr[i] = bBase + (uint32_t)(row * PADK + k4) * 4u;
        aPtr[i]  = A  + (size_t)(br + row) * DIM + k4;
        bPtr[i]  = Wt + (size_t)(bc + row) * DIM + k4;
    }
    const uint32_t stageA = (uint32_t)(BM * PADK) * 4u;
    const uint32_t stageB = (uint32_t)(BN * PADK) * 4u;

    float acc[4][4][4];
    #pragma unroll
    for (int mt = 0; mt < 4; mt++)
        #pragma unroll
        for (int nt = 0; nt < 4; nt++)
            #pragma unroll
            for (int i = 0; i < 4; i++) acc[mt][nt][i] = 0.0f;

    #pragma unroll
    for (int i = 0; i < 4; i++) { cp16(aAddr[i], aPtr[i]); cp16(bAddr[i], bPtr[i]); }
    cp_commit();

    const int KT = DIM / BK;   // 32
    for (int kt = 0; kt < KT; kt++) {
        const int buf = kt & 1;
        if (kt + 1 < KT) {
            const int nb = (kt + 1) & 1;
            const int k0 = (kt + 1) * BK;
            #pragma unroll
            for (int i = 0; i < 4; i++) {
                cp16(aAddr[i] + nb * stageA, aPtr[i] + k0);
                cp16(bAddr[i] + nb * stageB, bPtr[i] + k0);
            }
            cp_commit();
            cp_wait<1>();
        } else {
            cp_wait<0>();
        }
        __syncthreads();

        const uint32_t* Ab = As + buf * BM * PADK;
        const uint32_t* Bb = Bs + buf * BN * PADK;
        #pragma unroll
        for (int ks = 0; ks < BK; ks += 8) {
            uint32_t af[4][4];
            #pragma unroll
            for (int mt = 0; mt < 4; mt++) {
                const int r0 = wr * 64 + mt * 16 + g;
                af[mt][0] = Ab[(r0    ) * PADK + ks + tg    ];
                af[mt][1] = Ab[(r0 + 8) * PADK + ks + tg    ];
                af[mt][2] = Ab[(r0    ) * PADK + ks + tg + 4];
                af[mt][3] = Ab[(r0 + 8) * PADK + ks + tg + 4];
            }
            uint32_t bf[4][2];
            #pragma unroll
            for (int nt = 0; nt < 4; nt++) {
                const int n0 = wc * 32 + nt * 8 + g;
                bf[nt][0] = Bb[n0 * PADK + ks + tg    ];
                bf[nt][1] = Bb[n0 * PADK + ks + tg + 4];
            }
            #pragma unroll
            for (int mt = 0; mt < 4; mt++)
                #pragma unroll
                for (int nt = 0; nt < 4; nt++)
                    mma_tf32(acc[mt][nt], af[mt][0], af[mt][1], af[mt][2], af[mt][3],
                             bf[nt][0], bf[nt][1]);
        }
        __syncthreads();
    }

    // epilogue
    const float scale = (MODE == 1 && seg == 0) ? qscale : 1.0f;
    uint32_t* hs_out = (seg == 0) ? q_out : (seg == 1) ? k_out : v_out;
    #pragma unroll
    for (int mt = 0; mt < 4; mt++) {
        #pragma unroll
        for (int nt = 0; nt < 4; nt++) {
            const int nl = wc * 32 + nt * 8 + tg * 2;
            const float b0 = s_bias[nl], b1 = s_bias[nl + 1];
            #pragma unroll
            for (int half = 0; half < 2; half++) {
                const int m = br + wr * 64 + mt * 16 + g + half * 8;
                float vx = (acc[mt][nt][half * 2 + 0] + b0) * scale;
                float vy = (acc[mt][nt][half * 2 + 1] + b1) * scale;
                if (MODE == 0) {
                    const int n = bc + nl;
                    float2 v; v.x = vx; v.y = vy;
                    *(float2*)(f_out + (size_t)m * DIM + n) = v;
                } else {
                    const int nloc = (bc & 1023) + nl;
                    const int bb = m >> 11, q = m & 2047, h = nloc >> 6, d = nloc & 63;
                    uint2 u; u.x = f2tf32(vx); u.y = f2tf32(vy);
                    *(uint2*)(hs_out + (((size_t)bb * NH + h) * QLEN + q) * HD + d) = u;
                }
            }
        }
    }
}

// ---------------------------------------------------------------------------
// Tensor-core flash attention (unchanged from R8, passing).
// ---------------------------------------------------------------------------
#define PA 68
#define PV 72
#define ATTN_SMEM ((128*PA*2 + 64*PA + 64*PV + 3*128 + 64) * 4)

__global__ void __launch_bounds__(256) attn_mma(
    const uint32_t* __restrict__ Q, const uint32_t* __restrict__ K,
    const uint32_t* __restrict__ V, const float* __restrict__ mask,
    uint32_t* __restrict__ ctx)
{
    extern __shared__ unsigned char smraw[];
    uint32_t* Qs  = (uint32_t*)smraw;                          // 128 x PA
    float*    Ssh = (float*)(smraw + (128*PA)*4);              // 128 x PA
    uint32_t* Ks  = (uint32_t*)(smraw + (2*128*PA)*4);         // 64 x PA
    uint32_t* Vs  = (uint32_t*)(smraw + (2*128*PA + 64*PA)*4); // 64 x PV
    float*    msh  = (float*)(Vs + 64*PV);                     // 128
    float*    lsh  = msh + 128;                                // 128
    float*    alsh = lsh + 128;                                // 128
    float*    madd = alsh + 128;                               // 64

    const int tid  = threadIdx.x;
    const int wid  = tid >> 5;
    const int lane = tid & 31;
    const int g    = lane >> 2;
    const int tg   = lane & 3;
    const int wr   = wid >> 1;
    const int wc   = wid & 1;
    const int rb   = wr * 32;

    const int bh = blockIdx.x;
    const int b  = bh >> 4;
    const int h  = bh & 15;
    const int q0 = blockIdx.y * 128;

    const uint32_t* Qh = Q + (size_t)bh * QLEN * HD;
    const uint32_t* Kh = K + (size_t)bh * QLEN * HD;
    const uint32_t* Vh = V + (size_t)bh * QLEN * HD;
    const float* mb = mask + (size_t)b * QLEN;

    const uint32_t ksBase = smem_u32(Ks);
    const uint32_t vsBase = smem_u32(Vs);

    #pragma unroll
    for (int i = 0; i < 8; i++) {
        int idx = tid + i * 256;
        int r = idx >> 4, c4 = (idx & 15) * 4;
        *(uint4*)(&Qs[r * PA + c4]) = *(const uint4*)(Qh + (size_t)(q0 + r) * HD + c4);
    }
    if (tid < 128) { msh[tid] = -1e30f; lsh[tid] = 0.0f; }

    float o[2][4][4];
    #pragma unroll
    for (int mt = 0; mt < 2; mt++)
        #pragma unroll
        for (int nt = 0; nt < 4; nt++)
            #pragma unroll
            for (int i = 0; i < 4; i++) o[mt][nt][i] = 0.0f;

    for (int t = 0; t < QLEN / 64; t++) {
        const int kk0 = t * 64;
        __syncthreads();

        #pragma unroll
        for (int i = 0; i < 4; i++) {
            int idx = tid + i * 256;
            int r = idx >> 4, c4 = (idx & 15) * 4;
            cp16(ksBase + (uint32_t)(r * PA + c4) * 4u, Kh + (size_t)(kk0 + r) * HD + c4);
            cp16(vsBase + (uint32_t)(r * PV + c4) * 4u, Vh + (size_t)(kk0 + r) * HD + c4);
        }
        cp_commit();
        if (tid < 64) madd[tid] = -1e30f * (1.0f - mb[kk0 + tid]);
        cp_wait<0>();
        __syncthreads();

        float sacc[2][4][4];
        #pragma unroll
        for (int mt = 0; mt < 2; mt++)
            #pragma unroll
            for (int nt = 0; nt < 4; nt++)
                #pragma unroll
                for (int i = 0; i < 4; i++) sacc[mt][nt][i] = 0.0f;

        #pragma unroll
        for (int ks = 0; ks < 8; ks++) {
            const int k = ks * 8;
            uint32_t af[2][4];
            #pragma unroll
            for (int mt = 0; mt < 2; mt++) {
                const int r0 = rb + mt * 16 + g;
                af[mt][0] = Qs[(r0    ) * PA + k + tg    ];
                af[mt][1] = Qs[(r0 + 8) * PA + k + tg    ];
                af[mt][2] = Qs[(r0    ) * PA + k + tg + 4];
                af[mt][3] = Qs[(r0 + 8) * PA + k + tg + 4];
            }
            #pragma unroll
            for (int nt = 0; nt < 4; nt++) {
                const int n0 = wc * 32 + nt * 8 + g;
                uint32_t b0 = Ks[n0 * PA + k + tg    ];
                uint32_t b1 = Ks[n0 * PA + k + tg + 4];
                #pragma unroll
                for (int mt = 0; mt < 2; mt++)
                    mma_tf32(sacc[mt][nt], af[mt][0], af[mt][1], af[mt][2], af[mt][3], b0, b1);
            }
        }
        #pragma unroll
        for (int mt = 0; mt < 2; mt++)
            #pragma unroll
            for (int nt = 0; nt < 4; nt++) {
                const int col = wc * 32 + nt * 8 + tg * 2;
                const int r0  = rb + mt * 16 + g;
                Ssh[(r0    ) * PA + col    ] = sacc[mt][nt][0] + madd[col];
                Ssh[(r0    ) * PA + col + 1] = sacc[mt][nt][1] + madd[col + 1];
                Ssh[(r0 + 8) * PA + col    ] = sacc[mt][nt][2] + madd[col];
                Ssh[(r0 + 8) * PA + col + 1] = sacc[mt][nt][3] + madd[col + 1];
            }
        __syncthreads();

        {
            const int row = tid >> 1;
            const int sg  = tid & 1;
            float tmax = -1e30f;
            #pragma unroll
            for (int c = 0; c < 32; c++)
                tmax = fmaxf(tmax, Ssh[row * PA + sg + c * 2]);
            tmax = fmaxf(tmax, __shfl_xor_sync(0xffffffffu, tmax, 1));
            const float m_old = msh[row];
            const float m_new = fmaxf(m_old, tmax);
            float sum = 0.0f;
            #pragma unroll
            for (int c = 0; c < 32; c++) {
                float p = __expf(Ssh[row * PA + sg + c * 2] - m_new);
                Ssh[row * PA + sg + c * 2] = __uint_as_float(f2tf32(p));
                sum += p;
            }
            sum += __shfl_xor_sync(0xffffffffu, sum, 1);
            if (sg == 0) {
                const float alpha = __expf(m_old - m_new);
                msh[row]  = m_new;
                lsh[row]  = lsh[row] * alpha + sum;
                alsh[row] = alpha;
            }
        }
        __syncthreads();

        #pragma unroll
        for (int mt = 0; mt < 2; mt++) {
            const float a_lo = alsh[rb + mt * 16 + g];
            const float a_hi = alsh[rb + mt * 16 + g + 8];
            #pragma unroll
            for (int nt = 0; nt < 4; nt++) {
                o[mt][nt][0] *= a_lo; o[mt][nt][1] *= a_lo;
                o[mt][nt][2] *= a_hi; o[mt][nt][3] *= a_hi;
            }
        }
        #pragma unroll
        for (int ks = 0; ks < 8; ks++) {
            const int k = ks * 8;
            uint32_t af[2][4];
            #pragma unroll
            for (int mt = 0; mt < 2; mt++) {
                const int r0 = rb + mt * 16 + g;
                af[mt][0] = __float_as_uint(Ssh[(r0    ) * PA + k + tg    ]);
                af[mt][1] = __float_as_uint(Ssh[(r0 + 8) * PA + k + tg    ]);
                af[mt][2] = __float_as_uint(Ssh[(r0    ) * PA + k + tg + 4]);
                af[mt][3] = __float_as_uint(Ssh[(r0 + 8) * PA + k + tg + 4]);
            }
            #pragma unroll
            for (int nt = 0; nt < 4; nt++) {
                const int d0 = wc * 32 + nt * 8 + g;
                uint32_t b0 = Vs[(k + tg    ) * PV + d0];
                uint32_t b1 = Vs[(k + tg + 4) * PV + d0];
                #pragma unroll
                for (int mt = 0; mt < 2; mt++)
                    mma_tf32(o[mt][nt], af[mt][0], af[mt][1], af[mt][2], af[mt][3], b0, b1);
            }
        }
    }

    #pragma unroll
    for (int mt = 0; mt < 2; mt++) {
        const int r0 = rb + mt * 16 + g;
        const float inv_lo = 1.0f / lsh[r0];
        const float inv_hi = 1.0f / lsh[r0 + 8];
        #pragma unroll
        for (int nt = 0; nt < 4; nt++) {
            const int d = h * HD + wc * 32 + nt * 8 + tg * 2;
            const int m0 = q0 + r0;
            uint2 u0; u0.x = f2tf32(o[mt][nt][0] * inv_lo); u0.y = f2tf32(o[mt][nt][1] * inv_lo);
            *(uint2*)(&ctx[((size_t)(b * QLEN + m0)) * DIM + d]) = u0;
            uint2 u1; u1.x = f2tf32(o[mt][nt][2] * inv_hi); u1.y = f2tf32(o[mt][nt][3] * inv_hi);
            *(uint2*)(&ctx[((size_t)(b * QLEN + m0 + 8)) * DIM + d]) = u1;
        }
    }
}

// ---------------------------------------------------------------------------
extern "C" void kernel_launch(void* const* d_in, const int* in_sizes, int n_in,
                              void* d_out, int out_size)
{
    const float* x    = (const float*)d_in[0];
    const float* mask = (const float*)d_in[1];
    const float* Wq   = (const float*)d_in[2];
    const float* bq   = (const float*)d_in[3];
    const float* Wk   = (const float*)d_in[4];
    const float* bk   = (const float*)d_in[5];
    const float* Wv   = (const float*)d_in[6];
    const float* bv   = (const float*)d_in[7];
    const float* Wo   = (const float*)d_in[8];
    const float* bo   = (const float*)d_in[9];
    float* out = (float*)d_out;

    uint32_t *Qp, *Kp, *Vp, *Cp, *Xt, *WqkvT, *WoT;
    cudaGetSymbolAddress((void**)&Qp, g_Q);
    cudaGetSymbolAddress((void**)&Kp, g_K);
    cudaGetSymbolAddress((void**)&Vp, g_V);
    cudaGetSymbolAddress((void**)&Cp, g_C);
    cudaGetSymbolAddress((void**)&Xt, g_Xt);
    cudaGetSymbolAddress((void**)&WqkvT, g_WqkvT);
    cudaGetSymbolAddress((void**)&WoT, g_WoT);

    to_tf32<<<MTOT * DIM / 1024, 256>>>(x, Xt);
    transpose_w<<<dim3(32, 32, 4), dim3(32, 8)>>>(Wq, Wk, Wv, Wo, WqkvT, WoT);

    const float qscale = 1.0f / sqrtf((float)HD);

    cudaFuncSetAttribute(gemm_mma<1>, cudaFuncAttributeMaxDynamicSharedMemorySize, GEMM_SMEM);
    cudaFuncSetAttribute(gemm_mma<0>, cudaFuncAttributeMaxDynamicSharedMemorySize, GEMM_SMEM);

    // fused QKV projection: N = 3072
    gemm_mma<1><<<dim3(3 * DIM / 128, MTOT / 128), 256, GEMM_SMEM>>>(
        Xt, WqkvT, bq, bk, bv, Qp, Kp, Vp, nullptr, qscale);

    cudaFuncSetAttribute(attn_mma, cudaFuncAttributeMaxDynamicSharedMemorySize, ATTN_SMEM);
    attn_mma<<<dim3(BSZ * NH, QLEN / 128), 256, ATTN_SMEM>>>(Qp, Kp, Vp, mask, Cp);

    // output projection: fp32 out
    gemm_mma<0><<<dim3(DIM / 128, MTOT / 128), 256, GEMM_SMEM>>>(
        Cp, WoT, bo, nullptr, nullptr, nullptr, nullptr, nullptr, out, 1.0f);
}

// round 13
// speedup vs baseline: 4.4337x; 1.1010x over previous
#include <cuda_runtime.h>
#include <cstdint>
#include <math.h>

// Problem dims
#define BSZ   2
#define QLEN  2048
#define DIM   1024
#define NH    16
#define HD    64
#define MTOT  (BSZ*QLEN)   // 4096

// Scratch (device globals). tf32 bit patterns. V is stored [b,h,d,q] (transposed).
__device__ uint32_t g_Q[BSZ*NH*QLEN*HD];
__device__ uint32_t g_K[BSZ*NH*QLEN*HD];
__device__ uint32_t g_V[BSZ*NH*QLEN*HD];
__device__ uint32_t g_C[MTOT*DIM];
__device__ uint32_t g_Xt[MTOT*DIM];
__device__ uint32_t g_WqkvT[3*DIM*DIM];
__device__ uint32_t g_WoT[DIM*DIM];

__device__ __forceinline__ uint32_t smem_u32(const void* p) {
    uint32_t a;
    asm("{ .reg .u64 t; cvta.to.shared.u64 t, %1; cvt.u32.u64 %0, t; }" : "=r"(a) : "l"(p));
    return a;
}
__device__ __forceinline__ void cp16(uint32_t saddr, const void* gaddr) {
    asm volatile("cp.async.cg.shared.global [%0], [%1], 16;" :: "r"(saddr), "l"(gaddr));
}
__device__ __forceinline__ void cp_commit() { asm volatile("cp.async.commit_group;"); }
template<int N>
__device__ __forceinline__ void cp_wait() { asm volatile("cp.async.wait_group %0;" :: "n"(N)); }

__device__ __forceinline__ uint32_t f2tf32(float f) {
    uint32_t u;
    asm("cvt.rna.tf32.f32 %0, %1;" : "=r"(u) : "f"(f));
    return u;
}
__device__ __forceinline__ void mma_tf32(float c[4],
    uint32_t a0, uint32_t a1, uint32_t a2, uint32_t a3, uint32_t b0, uint32_t b1)
{
    asm volatile(
        "mma.sync.aligned.m16n8k8.row.col.f32.tf32.tf32.f32 "
        "{%0,%1,%2,%3}, {%4,%5,%6,%7}, {%8,%9}, {%0,%1,%2,%3};"
        : "+f"(c[0]), "+f"(c[1]), "+f"(c[2]), "+f"(c[3])
        : "r"(a0), "r"(a1), "r"(a2), "r"(a3), "r"(b0), "r"(b1));
}
// ldmatrix x4 of b16 8x8 matrices; on tf32 data each matrix = 8 rows x 4 tf32.
__device__ __forceinline__ void ldsm4(uint32_t r[4], uint32_t addr) {
    asm volatile("ldmatrix.sync.aligned.m8n8.x4.shared.b16 {%0,%1,%2,%3}, [%4];"
        : "=r"(r[0]), "=r"(r[1]), "=r"(r[2]), "=r"(r[3]) : "r"(addr));
}

// ---------------------------------------------------------------------------
// elementwise fp32 -> tf32 bits
// ---------------------------------------------------------------------------
__global__ void to_tf32(const float* __restrict__ in, uint32_t* __restrict__ out)
{
    int idx = (blockIdx.x * 256 + threadIdx.x) * 4;
    float4 v = *(const float4*)(in + idx);
    uint4 u;
    u.x = f2tf32(v.x); u.y = f2tf32(v.y); u.z = f2tf32(v.z); u.w = f2tf32(v.w);
    *(uint4*)(out + idx) = u;
}

// ---------------------------------------------------------------------------
// Batched 32x32 transpose of 4 weight matrices, emits tf32 bits.
// ---------------------------------------------------------------------------
__global__ void transpose_w(const float* __restrict__ w0, const float* __restrict__ w1,
                            const float* __restrict__ w2, const float* __restrict__ w3,
                            uint32_t* __restrict__ qkvT, uint32_t* __restrict__ woT)
{
    __shared__ float tile[32][33];
    const int z = blockIdx.z;
    const float* in = (z == 0) ? w0 : (z == 1) ? w1 : (z == 2) ? w2 : w3;
    uint32_t* out = (z < 3) ? (qkvT + (size_t)z * DIM * DIM) : woT;

    int x = blockIdx.x * 32 + threadIdx.x;
    int y = blockIdx.y * 32 + threadIdx.y;
    #pragma unroll
    for (int i = 0; i < 32; i += 8)
        tile[threadIdx.y + i][threadIdx.x] = in[(size_t)(y + i) * DIM + x];
    __syncthreads();
    int x2 = blockIdx.y * 32 + threadIdx.x;
    int y2 = blockIdx.x * 32 + threadIdx.y;
    #pragma unroll
    for (int i = 0; i < 32; i += 8)
        out[(size_t)(y2 + i) * DIM + x2] = f2tf32(tile[threadIdx.x][threadIdx.y + i]);
}

// ---------------------------------------------------------------------------
// tf32 mma.sync GEMM core, ldmatrix fragment loads. BK=32, dynamic smem.
// MODE 0: fp32 row-major out. MODE 1: QKV fused; V written [b,h,d,q].
// ---------------------------------------------------------------------------
#define BM 128
#define BN 128
#define BK 32
#define PADK 36
#define GEMM_SMEM (2 * 2 * BM * PADK * 4 + BN * 4)

template<int MODE>
__global__ void __launch_bounds__(256) gemm_mma(
    const uint32_t* __restrict__ A, const uint32_t* __restrict__ Wt,
    const float* __restrict__ bias0, const float* __restrict__ bias1,
    const float* __restrict__ bias2,
    uint32_t* __restrict__ q_out, uint32_t* __restrict__ k_out,
    uint32_t* __restrict__ v_out, float* __restrict__ f_out, float qscale)
{
    extern __shared__ unsigned char dynsm[];
    uint32_t* As = (uint32_t*)dynsm;
    uint32_t* Bs = As + 2 * BM * PADK;
    float* s_bias = (float*)(Bs + 2 * BN * PADK);

    const int tid  = threadIdx.x;
    const int wid  = tid >> 5;
    const int lane = tid & 31;
    const int g    = lane >> 2;
    const int tg   = lane & 3;
    const int wr   = wid >> 2;
    const int wc   = wid & 3;
    const int br   = blockIdx.y * BM;
    const int bc   = blockIdx.x * BN;
    const int seg  = (MODE == 1) ? (bc >> 10) : 0;

    if (tid < BN) {
        const float* bp = (MODE == 0) ? bias0
                         : (seg == 0) ? bias0 : (seg == 1) ? bias1 : bias2;
        s_bias[tid] = bp[(MODE == 1 ? (bc & 1023) : bc) + tid];
    }

    // ldmatrix per-lane offsets (words*4 = bytes)
    const uint32_t aRow = (lane & 7) + ((lane >> 3) & 1) * 8;   // A: m0/m1 rows, m2/m3 col+4
    const uint32_t aCol = (lane >> 4) * 4;
    const uint32_t aoffB = (aRow * PADK + aCol) * 4u;
    const uint32_t bRow = (lane & 7) + (lane >> 4) * 8;         // B: m0/m1 cols, m2/m3 rows+8
    const uint32_t bCol = ((lane >> 3) & 1) * 4;
    const uint32_t boffB = (bRow * PADK + bCol) * 4u;

    uint32_t aAddr[4], bAddr[4];
    const uint32_t* aPtr[4];
    const uint32_t* bPtr[4];
    const uint32_t aBase = smem_u32(As);
    const uint32_t bBase = smem_u32(Bs);
    #pragma unroll
    for (int i = 0; i < 4; i++) {
        int u = i * 256 + tid;
        int row = u >> 3;
        int k4  = (u & 7) * 4;
        aAddr[i] = aBase + (uint32_t)(row * PADK + k4) * 4u;
        bAddr[i] = bBase + (uint32_t)(row * PADK + k4) * 4u;
        aPtr[i]  = A  + (size_t)(br + row) * DIM + k4;
        bPtr[i]  = Wt + (size_t)(bc + row) * DIM + k4;
    }
    const uint32_t stageA = (uint32_t)(BM * PADK) * 4u;
    const uint32_t stageB = (uint32_t)(BN * PADK) * 4u;

    float acc[4][4][4];
    #pragma unroll
    for (int mt = 0; mt < 4; mt++)
        #pragma unroll
        for (int nt = 0; nt < 4; nt++)
            #pragma unroll
            for (int i = 0; i < 4; i++) acc[mt][nt][i] = 0.0f;

    #pragma unroll
    for (int i = 0; i < 4; i++) { cp16(aAddr[i], aPtr[i]); cp16(bAddr[i], bPtr[i]); }
    cp_commit();

    const int KT = DIM / BK;
    for (int kt = 0; kt < KT; kt++) {
        const int buf = kt & 1;
        if (kt + 1 < KT) {
            const int nb = (kt + 1) & 1;
            const int k0 = (kt + 1) * BK;
            #pragma unroll
            for (int i = 0; i < 4; i++) {
                cp16(aAddr[i] + nb * stageA, aPtr[i] + k0);
                cp16(bAddr[i] + nb * stageB, bPtr[i] + k0);
            }
            cp_commit();
            cp_wait<1>();
        } else {
            cp_wait<0>();
        }
        __syncthreads();

        const uint32_t AbB = aBase + buf * stageA + aoffB;
        const uint32_t BbB = bBase + buf * stageB + boffB;
        #pragma unroll
        for (int ks = 0; ks < BK; ks += 8) {
            uint32_t af[4][4];
            #pragma unroll
            for (int mt = 0; mt < 4; mt++)
                ldsm4(af[mt], AbB + (uint32_t)(((wr * 64 + mt * 16) * PADK + ks) * 4));
            uint32_t bf[4][2];
            #pragma unroll
            for (int np = 0; np < 2; np++) {
                uint32_t t[4];
                ldsm4(t, BbB + (uint32_t)(((wc * 32 + np * 16) * PADK + ks) * 4));
                bf[np * 2][0] = t[0]; bf[np * 2][1] = t[1];
                bf[np * 2 + 1][0] = t[2]; bf[np * 2 + 1][1] = t[3];
            }
            #pragma unroll
            for (int mt = 0; mt < 4; mt++)
                #pragma unroll
                for (int nt = 0; nt < 4; nt++)
                    mma_tf32(acc[mt][nt], af[mt][0], af[mt][1], af[mt][2], af[mt][3],
                             bf[nt][0], bf[nt][1]);
        }
        __syncthreads();
    }

    // epilogue
    const float scale = (MODE == 1 && seg == 0) ? qscale : 1.0f;
    uint32_t* hs_out = (seg == 0) ? q_out : (seg == 1) ? k_out : v_out;
    #pragma unroll
    for (int mt = 0; mt < 4; mt++) {
        #pragma unroll
        for (int nt = 0; nt < 4; nt++) {
            const int nl = wc * 32 + nt * 8 + tg * 2;
            const float b0 = s_bias[nl], b1 = s_bias[nl + 1];
            #pragma unroll
            for (int half = 0; half < 2; half++) {
                const int m = br + wr * 64 + mt * 16 + g + half * 8;
                float vx = (acc[mt][nt][half * 2 + 0] + b0) * scale;
                float vy = (acc[mt][nt][half * 2 + 1] + b1) * scale;
                if (MODE == 0) {
                    const int n = bc + nl;
                    float2 v; v.x = vx; v.y = vy;
                    *(float2*)(f_out + (size_t)m * DIM + n) = v;
                } else {
                    const int nloc = (bc & 1023) + nl;
                    const int bb = m >> 11, q = m & 2047, h = nloc >> 6, d = nloc & 63;
                    if (seg == 2) {
                        // V transposed: [b,h,d,q]
                        uint32_t* vb = hs_out + ((size_t)(bb * NH + h) * HD) * QLEN;
                        vb[(size_t)d * QLEN + q]       = f2tf32(vx);
                        vb[(size_t)(d + 1) * QLEN + q] = f2tf32(vy);
                    } else {
                        uint2 u; u.x = f2tf32(vx); u.y = f2tf32(vy);
                        *(uint2*)(hs_out + (((size_t)bb * NH + h) * QLEN + q) * HD + d) = u;
                    }
                }
            }
        }
    }
}

// ---------------------------------------------------------------------------
// Tensor-core flash attention, ldmatrix fragment loads.
// V arrives [b,h,d,q]; Vs staged n-major (d rows) so LDSM works for PV B.
// ---------------------------------------------------------------------------
#define PA 68
#define PV 68
#define ATTN_SMEM ((128*PA*2 + 64*PA + 64*PV + 3*128 + 64) * 4)

__global__ void __launch_bounds__(256) attn_mma(
    const uint32_t* __restrict__ Q, const uint32_t* __restrict__ K,
    const uint32_t* __restrict__ V, const float* __restrict__ mask,
    uint32_t* __restrict__ ctx)
{
    extern __shared__ unsigned char smraw[];
    uint32_t* Qs  = (uint32_t*)smraw;                          // 128 x PA
    float*    Ssh = (float*)(smraw + (128*PA)*4);              // 128 x PA
    uint32_t* Ks  = (uint32_t*)(smraw + (2*128*PA)*4);         // 64 x PA (keys n-major)
    uint32_t* Vs  = (uint32_t*)(smraw + (2*128*PA + 64*PA)*4); // 64 x PV (d-major rows)
    float*    msh  = (float*)(Vs + 64*PV);
    float*    lsh  = msh + 128;
    float*    alsh = lsh + 128;
    float*    madd = alsh + 128;

    const int tid  = threadIdx.x;
    const int wid  = tid >> 5;
    const int lane = tid & 31;
    const int g    = lane >> 2;
    const int tg   = lane & 3;
    const int wr   = wid >> 1;
    const int wc   = wid & 1;
    const int rb   = wr * 32;

    const int bh = blockIdx.x;
    const int b  = bh >> 4;
    const int h  = bh & 15;
    const int q0 = blockIdx.y * 128;

    const uint32_t* Qh = Q + (size_t)bh * QLEN * HD;
    const uint32_t* Kh = K + (size_t)bh * QLEN * HD;
    const uint32_t* Vh = V + (size_t)bh * QLEN * HD;   // [d][q]
    const float* mb = mask + (size_t)b * QLEN;

    const uint32_t qsBase = smem_u32(Qs);
    const uint32_t ssBase = smem_u32(Ssh);
    const uint32_t ksBase = smem_u32(Ks);
    const uint32_t vsBase = smem_u32(Vs);

    // ldmatrix per-lane offsets
    const uint32_t aRow = (lane & 7) + ((lane >> 3) & 1) * 8;
    const uint32_t aCol = (lane >> 4) * 4;
    const uint32_t aoffA = (aRow * PA + aCol) * 4u;
    const uint32_t bRow = (lane & 7) + (lane >> 4) * 8;
    const uint32_t bCol = ((lane >> 3) & 1) * 4;
    const uint32_t boffK = (bRow * PA + bCol) * 4u;
    const uint32_t boffV = (bRow * PV + bCol) * 4u;

    // stage Q (bit copy)
    #pragma unroll
    for (int i = 0; i < 8; i++) {
        int idx = tid + i * 256;
        int r = idx >> 4, c4 = (idx & 15) * 4;
        *(uint4*)(&Qs[r * PA + c4]) = *(const uint4*)(Qh + (size_t)(q0 + r) * HD + c4);
    }
    if (tid < 128) { msh[tid] = -1e30f; lsh[tid] = 0.0f; }

    float o[2][4][4];
    #pragma unroll
    for (int mt = 0; mt < 2; mt++)
        #pragma unroll
        for (int nt = 0; nt < 4; nt++)
            #pragma unroll
            for (int i = 0; i < 4; i++) o[mt][nt][i] = 0.0f;

    for (int t = 0; t < QLEN / 64; t++) {
        const int kk0 = t * 64;
        __syncthreads();

        // K: rows = key index (n-major). V: rows = d (n-major for PV B).
        #pragma unroll
        for (int i = 0; i < 4; i++) {
            int idx = tid + i * 256;
            int r = idx >> 4, c4 = (idx & 15) * 4;
            cp16(ksBase + (uint32_t)(r * PA + c4) * 4u, Kh + (size_t)(kk0 + r) * HD + c4);
            cp16(vsBase + (uint32_t)(r * PV + c4) * 4u, Vh + (size_t)r * QLEN + kk0 + c4);
        }
        cp_commit();
        if (tid < 64) madd[tid] = -1e30f * (1.0f - mb[kk0 + tid]);
        cp_wait<0>();
        __syncthreads();

        // S = Q @ K^T
        float sacc[2][4][4];
        #pragma unroll
        for (int mt = 0; mt < 2; mt++)
            #pragma unroll
            for (int nt = 0; nt < 4; nt++)
                #pragma unroll
                for (int i = 0; i < 4; i++) sacc[mt][nt][i] = 0.0f;

        #pragma unroll
        for (int ks = 0; ks < 8; ks++) {
            const int k = ks * 8;
            uint32_t af[2][4];
            #pragma unroll
            for (int mt = 0; mt < 2; mt++)
                ldsm4(af[mt], qsBase + aoffA + (uint32_t)(((rb + mt * 16) * PA + k) * 4));
            uint32_t bf[4][2];
            #pragma unroll
            for (int np = 0; np < 2; np++) {
                uint32_t tt[4];
                ldsm4(tt, ksBase + boffK + (uint32_t)(((wc * 32 + np * 16) * PA + k) * 4));
                bf[np * 2][0] = tt[0]; bf[np * 2][1] = tt[1];
                bf[np * 2 + 1][0] = tt[2]; bf[np * 2 + 1][1] = tt[3];
            }
            #pragma unroll
            for (int nt = 0; nt < 4; nt++)
                #pragma unroll
                for (int mt = 0; mt < 2; mt++)
                    mma_tf32(sacc[mt][nt], af[mt][0], af[mt][1], af[mt][2], af[mt][3],
                             bf[nt][0], bf[nt][1]);
        }
        #pragma unroll
        for (int mt = 0; mt < 2; mt++)
            #pragma unroll
            for (int nt = 0; nt < 4; nt++) {
                const int col = wc * 32 + nt * 8 + tg * 2;
                const int r0  = rb + mt * 16 + g;
                Ssh[(r0    ) * PA + col    ] = sacc[mt][nt][0] + madd[col];
                Ssh[(r0    ) * PA + col + 1] = sacc[mt][nt][1] + madd[col + 1];
                Ssh[(r0 + 8) * PA + col    ] = sacc[mt][nt][2] + madd[col];
                Ssh[(r0 + 8) * PA + col + 1] = sacc[mt][nt][3] + madd[col + 1];
            }
        __syncthreads();

        // online softmax: 2 threads per row; write P as tf32 bits
        {
            const int row = tid >> 1;
            const int sg  = tid & 1;
            float tmax = -1e30f;
            #pragma unroll
            for (int c = 0; c < 32; c++)
                tmax = fmaxf(tmax, Ssh[row * PA + sg + c * 2]);
            tmax = fmaxf(tmax, __shfl_xor_sync(0xffffffffu, tmax, 1));
            const float m_old = msh[row];
            const float m_new = fmaxf(m_old, tmax);
            float sum = 0.0f;
            #pragma unroll
            for (int c = 0; c < 32; c++) {
                float p = __expf(Ssh[row * PA + sg + c * 2] - m_new);
                Ssh[row * PA + sg + c * 2] = __uint_as_float(f2tf32(p));
                sum += p;
            }
            sum += __shfl_xor_sync(0xffffffffu, sum, 1);
            if (sg == 0) {
                const float alpha = __expf(m_old - m_new);
                msh[row]  = m_new;
                lsh[row]  = lsh[row] * alpha + sum;
                alsh[row] = alpha;
            }
        }
        __syncthreads();

        // rescale O, then O += P @ V
        #pragma unroll
        for (int mt = 0; mt < 2; mt++) {
            const float a_lo = alsh[rb + mt * 16 + g];
            const float a_hi = alsh[rb + mt * 16 + g + 8];
            #pragma unroll
            for (int nt = 0; nt < 4; nt++) {
                o[mt][nt][0] *= a_lo; o[mt][nt][1] *= a_lo;
                o[mt][nt][2] *= a_hi; o[mt][nt][3] *= a_hi;
            }
        }
        #pragma unroll
        for (int ks = 0; ks < 8; ks++) {
            const int k = ks * 8;
            uint32_t af[2][4];
            #pragma unroll
            for (int mt = 0; mt < 2; mt++)
                ldsm4(af[mt], ssBase + aoffA + (uint32_t)(((rb + mt * 16) * PA + k) * 4));
            uint32_t bf[4][2];
            #pragma unroll
            for (int np = 0; np < 2; np++) {
                uint32_t tt[4];
                ldsm4(tt, vsBase + boffV + (uint32_t)(((wc * 32 + np * 16) * PV + k) * 4));
                bf[np * 2][0] = tt[0]; bf[np * 2][1] = tt[1];
                bf[np * 2 + 1][0] = tt[2]; bf[np * 2 + 1][1] = tt[3];
            }
            #pragma unroll
            for (int nt = 0; nt < 4; nt++)
                #pragma unroll
                for (int mt = 0; mt < 2; mt++)
                    mma_tf32(o[mt][nt], af[mt][0], af[mt][1], af[mt][2], af[mt][3],
                             bf[nt][0], bf[nt][1]);
        }
    }

    // write context [b, q, h*HD + d] as tf32 bits
    #pragma unroll
    for (int mt = 0; mt < 2; mt++) {
        const int r0 = rb + mt * 16 + g;
        const float inv_lo = 1.0f / lsh[r0];
        const float inv_hi = 1.0f / lsh[r0 + 8];
        #pragma unroll
        for (int nt = 0; nt < 4; nt++) {
            const int d = h * HD + wc * 32 + nt * 8 + tg * 2;
            const int m0 = q0 + r0;
            uint2 u0; u0.x = f2tf32(o[mt][nt][0] * inv_lo); u0.y = f2tf32(o[mt][nt][1] * inv_lo);
            *(uint2*)(&ctx[((size_t)(b * QLEN + m0)) * DIM + d]) = u0;
            uint2 u1; u1.x = f2tf32(o[mt][nt][2] * inv_hi); u1.y = f2tf32(o[mt][nt][3] * inv_hi);
            *(uint2*)(&ctx[((size_t)(b * QLEN + m0 + 8)) * DIM + d]) = u1;
        }
    }
}

// ---------------------------------------------------------------------------
extern "C" void kernel_launch(void* const* d_in, const int* in_sizes, int n_in,
                              void* d_out, int out_size)
{
    const float* x    = (const float*)d_in[0];
    const float* mask = (const float*)d_in[1];
    const float* Wq   = (const float*)d_in[2];
    const float* bq   = (const float*)d_in[3];
    const float* Wk   = (const float*)d_in[4];
    const float* bk   = (const float*)d_in[5];
    const float* Wv   = (const float*)d_in[6];
    const float* bv   = (const float*)d_in[7];
    const float* Wo   = (const float*)d_in[8];
    const float* bo   = (const float*)d_in[9];
    float* out = (float*)d_out;

    uint32_t *Qp, *Kp, *Vp, *Cp, *Xt, *WqkvT, *WoT;
    cudaGetSymbolAddress((void**)&Qp, g_Q);
    cudaGetSymbolAddress((void**)&Kp, g_K);
    cudaGetSymbolAddress((void**)&Vp, g_V);
    cudaGetSymbolAddress((void**)&Cp, g_C);
    cudaGetSymbolAddress((void**)&Xt, g_Xt);
    cudaGetSymbolAddress((void**)&WqkvT, g_WqkvT);
    cudaGetSymbolAddress((void**)&WoT, g_WoT);

    to_tf32<<<MTOT * DIM / 1024, 256>>>(x, Xt);
    transpose_w<<<dim3(32, 32, 4), dim3(32, 8)>>>(Wq, Wk, Wv, Wo, WqkvT, WoT);

    const float qscale = 1.0f / sqrtf((float)HD);

    cudaFuncSetAttribute(gemm_mma<1>, cudaFuncAttributeMaxDynamicSharedMemorySize, GEMM_SMEM);
    cudaFuncSetAttribute(gemm_mma<0>, cudaFuncAttributeMaxDynamicSharedMemorySize, GEMM_SMEM);

    // fused QKV projection: N = 3072
    gemm_mma<1><<<dim3(3 * DIM / 128, MTOT / 128), 256, GEMM_SMEM>>>(
        Xt, WqkvT, bq, bk, bv, Qp, Kp, Vp, nullptr, qscale);

    cudaFuncSetAttribute(attn_mma, cudaFuncAttributeMaxDynamicSharedMemorySize, ATTN_SMEM);
    attn_mma<<<dim3(BSZ * NH, QLEN / 128), 256, ATTN_SMEM>>>(Qp, Kp, Vp, mask, Cp);

    // output projection: fp32 out
    gemm_mma<0><<<dim3(DIM / 128, MTOT / 128), 256, GEMM_SMEM>>>(
        Cp, WoT, bo, nullptr, nullptr, nullptr, nullptr, nullptr, out, 1.0f);
}

// round 14
// speedup vs baseline: 4.6703x; 1.0533x over previous
#include <cuda_runtime.h>
#include <cstdint>
#include <math.h>

// Problem dims
#define BSZ   2
#define QLEN  2048
#define DIM   1024
#define NH    16
#define HD    64
#define MTOT  (BSZ*QLEN)   // 4096

// Scratch (device globals). tf32 bit patterns. V is stored [b,h,d,q] (transposed).
__device__ uint32_t g_Q[BSZ*NH*QLEN*HD];
__device__ uint32_t g_K[BSZ*NH*QLEN*HD];
__device__ uint32_t g_V[BSZ*NH*QLEN*HD];
__device__ uint32_t g_C[MTOT*DIM];
__device__ uint32_t g_Xt[MTOT*DIM];
__device__ uint32_t g_WqkvT[3*DIM*DIM];
__device__ uint32_t g_WoT[DIM*DIM];

__device__ __forceinline__ uint32_t smem_u32(const void* p) {
    uint32_t a;
    asm("{ .reg .u64 t; cvta.to.shared.u64 t, %1; cvt.u32.u64 %0, t; }" : "=r"(a) : "l"(p));
    return a;
}
__device__ __forceinline__ void cp16(uint32_t saddr, const void* gaddr) {
    asm volatile("cp.async.cg.shared.global [%0], [%1], 16;" :: "r"(saddr), "l"(gaddr));
}
__device__ __forceinline__ void cp_commit() { asm volatile("cp.async.commit_group;"); }
template<int N>
__device__ __forceinline__ void cp_wait() { asm volatile("cp.async.wait_group %0;" :: "n"(N)); }

__device__ __forceinline__ uint32_t f2tf32(float f) {
    uint32_t u;
    asm("cvt.rna.tf32.f32 %0, %1;" : "=r"(u) : "f"(f));
    return u;
}
__device__ __forceinline__ void mma_tf32(float c[4],
    uint32_t a0, uint32_t a1, uint32_t a2, uint32_t a3, uint32_t b0, uint32_t b1)
{
    asm volatile(
        "mma.sync.aligned.m16n8k8.row.col.f32.tf32.tf32.f32 "
        "{%0,%1,%2,%3}, {%4,%5,%6,%7}, {%8,%9}, {%0,%1,%2,%3};"
        : "+f"(c[0]), "+f"(c[1]), "+f"(c[2]), "+f"(c[3])
        : "r"(a0), "r"(a1), "r"(a2), "r"(a3), "r"(b0), "r"(b1));
}
// ldmatrix x4 of b16 8x8 matrices; on tf32 data each matrix = 8 rows x 4 tf32.
__device__ __forceinline__ void ldsm4(uint32_t r[4], uint32_t addr) {
    asm volatile("ldmatrix.sync.aligned.m8n8.x4.shared.b16 {%0,%1,%2,%3}, [%4];"
        : "=r"(r[0]), "=r"(r[1]), "=r"(r[2]), "=r"(r[3]) : "r"(addr));
}

// ---------------------------------------------------------------------------
// elementwise fp32 -> tf32 bits
// ---------------------------------------------------------------------------
__global__ void to_tf32(const float* __restrict__ in, uint32_t* __restrict__ out)
{
    int idx = (blockIdx.x * 256 + threadIdx.x) * 4;
    float4 v = *(const float4*)(in + idx);
    uint4 u;
    u.x = f2tf32(v.x); u.y = f2tf32(v.y); u.z = f2tf32(v.z); u.w = f2tf32(v.w);
    *(uint4*)(out + idx) = u;
}

// ---------------------------------------------------------------------------
// Batched 32x32 transpose of 4 weight matrices, emits tf32 bits.
// ---------------------------------------------------------------------------
__global__ void transpose_w(const float* __restrict__ w0, const float* __restrict__ w1,
                            const float* __restrict__ w2, const float* __restrict__ w3,
                            uint32_t* __restrict__ qkvT, uint32_t* __restrict__ woT)
{
    __shared__ float tile[32][33];
    const int z = blockIdx.z;
    const float* in = (z == 0) ? w0 : (z == 1) ? w1 : (z == 2) ? w2 : w3;
    uint32_t* out = (z < 3) ? (qkvT + (size_t)z * DIM * DIM) : woT;

    int x = blockIdx.x * 32 + threadIdx.x;
    int y = blockIdx.y * 32 + threadIdx.y;
    #pragma unroll
    for (int i = 0; i < 32; i += 8)
        tile[threadIdx.y + i][threadIdx.x] = in[(size_t)(y + i) * DIM + x];
    __syncthreads();
    int x2 = blockIdx.y * 32 + threadIdx.x;
    int y2 = blockIdx.x * 32 + threadIdx.y;
    #pragma unroll
    for (int i = 0; i < 32; i += 8)
        out[(size_t)(y2 + i) * DIM + x2] = f2tf32(tile[threadIdx.x][threadIdx.y + i]);
}

// ---------------------------------------------------------------------------
// tf32 mma.sync GEMM core, ldmatrix fragment loads. BK=32, dynamic smem.
// MODE 0: fp32 row-major out. MODE 1: QKV fused; V written [b,h,d,q].
// ---------------------------------------------------------------------------
#define BM 128
#define BN 128
#define BK 32
#define PADK 36
#define GEMM_SMEM (2 * 2 * BM * PADK * 4 + BN * 4)

template<int MODE>
__global__ void __launch_bounds__(256) gemm_mma(
    const uint32_t* __restrict__ A, const uint32_t* __restrict__ Wt,
    const float* __restrict__ bias0, const float* __restrict__ bias1,
    const float* __restrict__ bias2,
    uint32_t* __restrict__ q_out, uint32_t* __restrict__ k_out,
    uint32_t* __restrict__ v_out, float* __restrict__ f_out, float qscale)
{
    extern __shared__ unsigned char dynsm[];
    uint32_t* As = (uint32_t*)dynsm;
    uint32_t* Bs = As + 2 * BM * PADK;
    float* s_bias = (float*)(Bs + 2 * BN * PADK);

    const int tid  = threadIdx.x;
    const int wid  = tid >> 5;
    const int lane = tid & 31;
    const int g    = lane >> 2;
    const int tg   = lane & 3;
    const int wr   = wid >> 2;
    const int wc   = wid & 3;
    const int br   = blockIdx.y * BM;
    const int bc   = blockIdx.x * BN;
    const int seg  = (MODE == 1) ? (bc >> 10) : 0;

    if (tid < BN) {
        const float* bp = (MODE == 0) ? bias0
                         : (seg == 0) ? bias0 : (seg == 1) ? bias1 : bias2;
        s_bias[tid] = bp[(MODE == 1 ? (bc & 1023) : bc) + tid];
    }

    const uint32_t aRow = (lane & 7) + ((lane >> 3) & 1) * 8;
    const uint32_t aCol = (lane >> 4) * 4;
    const uint32_t aoffB = (aRow * PADK + aCol) * 4u;
    const uint32_t bRow = (lane & 7) + (lane >> 4) * 8;
    const uint32_t bCol = ((lane >> 3) & 1) * 4;
    const uint32_t boffB = (bRow * PADK + bCol) * 4u;

    uint32_t aAddr[4], bAddr[4];
    const uint32_t* aPtr[4];
    const uint32_t* bPtr[4];
    const uint32_t aBase = smem_u32(As);
    const uint32_t bBase = smem_u32(Bs);
    #pragma unroll
    for (int i = 0; i < 4; i++) {
        int u = i * 256 + tid;
        int row = u >> 3;
        int k4  = (u & 7) * 4;
        aAddr[i] = aBase + (uint32_t)(row * PADK + k4) * 4u;
        bAddr[i] = bBase + (uint32_t)(row * PADK + k4) * 4u;
        aPtr[i]  = A  + (size_t)(br + row) * DIM + k4;
        bPtr[i]  = Wt + (size_t)(bc + row) * DIM + k4;
    }
    const uint32_t stageA = (uint32_t)(BM * PADK) * 4u;
    const uint32_t stageB = (uint32_t)(BN * PADK) * 4u;

    float acc[4][4][4];
    #pragma unroll
    for (int mt = 0; mt < 4; mt++)
        #pragma unroll
        for (int nt = 0; nt < 4; nt++)
            #pragma unroll
            for (int i = 0; i < 4; i++) acc[mt][nt][i] = 0.0f;

    #pragma unroll
    for (int i = 0; i < 4; i++) { cp16(aAddr[i], aPtr[i]); cp16(bAddr[i], bPtr[i]); }
    cp_commit();

    const int KT = DIM / BK;
    for (int kt = 0; kt < KT; kt++) {
        const int buf = kt & 1;
        if (kt + 1 < KT) {
            const int nb = (kt + 1) & 1;
            const int k0 = (kt + 1) * BK;
            #pragma unroll
            for (int i = 0; i < 4; i++) {
                cp16(aAddr[i] + nb * stageA, aPtr[i] + k0);
                cp16(bAddr[i] + nb * stageB, bPtr[i] + k0);
            }
            cp_commit();
            cp_wait<1>();
        } else {
            cp_wait<0>();
        }
        __syncthreads();

        const uint32_t AbB = aBase + buf * stageA + aoffB;
        const uint32_t BbB = bBase + buf * stageB + boffB;
        #pragma unroll
        for (int ks = 0; ks < BK; ks += 8) {
            uint32_t af[4][4];
            #pragma unroll
            for (int mt = 0; mt < 4; mt++)
                ldsm4(af[mt], AbB + (uint32_t)(((wr * 64 + mt * 16) * PADK + ks) * 4));
            uint32_t bf[4][2];
            #pragma unroll
            for (int np = 0; np < 2; np++) {
                uint32_t t[4];
                ldsm4(t, BbB + (uint32_t)(((wc * 32 + np * 16) * PADK + ks) * 4));
                bf[np * 2][0] = t[0]; bf[np * 2][1] = t[1];
                bf[np * 2 + 1][0] = t[2]; bf[np * 2 + 1][1] = t[3];
            }
            #pragma unroll
            for (int mt = 0; mt < 4; mt++)
                #pragma unroll
                for (int nt = 0; nt < 4; nt++)
                    mma_tf32(acc[mt][nt], af[mt][0], af[mt][1], af[mt][2], af[mt][3],
                             bf[nt][0], bf[nt][1]);
        }
        __syncthreads();
    }

    const float scale = (MODE == 1 && seg == 0) ? qscale : 1.0f;
    uint32_t* hs_out = (seg == 0) ? q_out : (seg == 1) ? k_out : v_out;
    #pragma unroll
    for (int mt = 0; mt < 4; mt++) {
        #pragma unroll
        for (int nt = 0; nt < 4; nt++) {
            const int nl = wc * 32 + nt * 8 + tg * 2;
            const float b0 = s_bias[nl], b1 = s_bias[nl + 1];
            #pragma unroll
            for (int half = 0; half < 2; half++) {
                const int m = br + wr * 64 + mt * 16 + g + half * 8;
                float vx = (acc[mt][nt][half * 2 + 0] + b0) * scale;
                float vy = (acc[mt][nt][half * 2 + 1] + b1) * scale;
                if (MODE == 0) {
                    const int n = bc + nl;
                    float2 v; v.x = vx; v.y = vy;
                    *(float2*)(f_out + (size_t)m * DIM + n) = v;
                } else {
                    const int nloc = (bc & 1023) + nl;
                    const int bb = m >> 11, q = m & 2047, h = nloc >> 6, d = nloc & 63;
                    if (seg == 2) {
                        uint32_t* vb = hs_out + ((size_t)(bb * NH + h) * HD) * QLEN;
                        vb[(size_t)d * QLEN + q]       = f2tf32(vx);
                        vb[(size_t)(d + 1) * QLEN + q] = f2tf32(vy);
                    } else {
                        uint2 u; u.x = f2tf32(vx); u.y = f2tf32(vy);
                        *(uint2*)(hs_out + (((size_t)bb * NH + h) * QLEN + q) * HD + d) = u;
                    }
                }
            }
        }
    }
}

// ---------------------------------------------------------------------------
// Tensor-core flash attention; register-resident softmax.
// S stays in accumulator fragments; row max/sum via quad shfl + 2x128 smem
// half-exchange; P written once (tf32 bits) for the PV ldmatrix loads.
// ---------------------------------------------------------------------------
#define PA 68
#define PV 68
#define ATTN_SMEM ((128*PA*2 + 64*PA + 64*PV + 2*128 + 2*256 + 64) * 4)

__global__ void __launch_bounds__(256) attn_mma(
    const uint32_t* __restrict__ Q, const uint32_t* __restrict__ K,
    const uint32_t* __restrict__ V, const float* __restrict__ mask,
    uint32_t* __restrict__ ctx)
{
    extern __shared__ unsigned char smraw[];
    uint32_t* Qs  = (uint32_t*)smraw;                          // 128 x PA
    float*    Ssh = (float*)(smraw + (128*PA)*4);              // 128 x PA (P bits)
    uint32_t* Ks  = (uint32_t*)(smraw + (2*128*PA)*4);         // 64 x PA
    uint32_t* Vs  = (uint32_t*)(smraw + (2*128*PA + 64*PA)*4); // 64 x PV (d-major)
    float*    msh  = (float*)(Vs + 64*PV);                     // 128
    float*    lsh  = msh + 128;                                // 128
    float*    wmax = lsh + 128;                                // 2 x 128
    float*    wsum = wmax + 256;                               // 2 x 128
    float*    madd = wsum + 256;                               // 64

    const int tid  = threadIdx.x;
    const int wid  = tid >> 5;
    const int lane = tid & 31;
    const int g    = lane >> 2;
    const int tg   = lane & 3;
    const int wr   = wid >> 1;
    const int wc   = wid & 1;
    const int rb   = wr * 32;

    const int bh = blockIdx.x;
    const int b  = bh >> 4;
    const int h  = bh & 15;
    const int q0 = blockIdx.y * 128;

    const uint32_t* Qh = Q + (size_t)bh * QLEN * HD;
    const uint32_t* Kh = K + (size_t)bh * QLEN * HD;
    const uint32_t* Vh = V + (size_t)bh * QLEN * HD;   // [d][q]
    const float* mb = mask + (size_t)b * QLEN;

    const uint32_t qsBase = smem_u32(Qs);
    const uint32_t ssBase = smem_u32(Ssh);
    const uint32_t ksBase = smem_u32(Ks);
    const uint32_t vsBase = smem_u32(Vs);

    const uint32_t aRow = (lane & 7) + ((lane >> 3) & 1) * 8;
    const uint32_t aCol = (lane >> 4) * 4;
    const uint32_t aoffA = (aRow * PA + aCol) * 4u;
    const uint32_t bRow = (lane & 7) + (lane >> 4) * 8;
    const uint32_t bCol = ((lane >> 3) & 1) * 4;
    const uint32_t boffK = (bRow * PA + bCol) * 4u;
    const uint32_t boffV = (bRow * PV + bCol) * 4u;

    // stage Q (bit copy)
    #pragma unroll
    for (int i = 0; i < 8; i++) {
        int idx = tid + i * 256;
        int r = idx >> 4, c4 = (idx & 15) * 4;
        *(uint4*)(&Qs[r * PA + c4]) = *(const uint4*)(Qh + (size_t)(q0 + r) * HD + c4);
    }
    if (tid < 128) { msh[tid] = -1e30f; lsh[tid] = 0.0f; }

    float o[2][4][4];
    #pragma unroll
    for (int mt = 0; mt < 2; mt++)
        #pragma unroll
        for (int nt = 0; nt < 4; nt++)
            #pragma unroll
            for (int i = 0; i < 4; i++) o[mt][nt][i] = 0.0f;

    for (int t = 0; t < QLEN / 64; t++) {
        const int kk0 = t * 64;
        __syncthreads();   // A: prev PV done; msh/lsh updates visible

        #pragma unroll
        for (int i = 0; i < 4; i++) {
            int idx = tid + i * 256;
            int r = idx >> 4, c4 = (idx & 15) * 4;
            cp16(ksBase + (uint32_t)(r * PA + c4) * 4u, Kh + (size_t)(kk0 + r) * HD + c4);
            cp16(vsBase + (uint32_t)(r * PV + c4) * 4u, Vh + (size_t)r * QLEN + kk0 + c4);
        }
        cp_commit();
        if (tid < 64) madd[tid] = -1e30f * (1.0f - mb[kk0 + tid]);
        cp_wait<0>();
        __syncthreads();   // B

        // mask values for this lane's 8 columns
        float2 ma[4];
        #pragma unroll
        for (int nt = 0; nt < 4; nt++)
            ma[nt] = *(float2*)(&madd[wc * 32 + nt * 8 + tg * 2]);

        // S = Q @ K^T
        float sacc[2][4][4];
        #pragma unroll
        for (int mt = 0; mt < 2; mt++)
            #pragma unroll
            for (int nt = 0; nt < 4; nt++)
                #pragma unroll
                for (int i = 0; i < 4; i++) sacc[mt][nt][i] = 0.0f;

        #pragma unroll
        for (int ks = 0; ks < 8; ks++) {
            const int k = ks * 8;
            uint32_t af[2][4];
            #pragma unroll
            for (int mt = 0; mt < 2; mt++)
                ldsm4(af[mt], qsBase + aoffA + (uint32_t)(((rb + mt * 16) * PA + k) * 4));
            uint32_t bf[4][2];
            #pragma unroll
            for (int np = 0; np < 2; np++) {
                uint32_t tt[4];
                ldsm4(tt, ksBase + boffK + (uint32_t)(((wc * 32 + np * 16) * PA + k) * 4));
                bf[np * 2][0] = tt[0]; bf[np * 2][1] = tt[1];
                bf[np * 2 + 1][0] = tt[2]; bf[np * 2 + 1][1] = tt[3];
            }
            #pragma unroll
            for (int nt = 0; nt < 4; nt++)
                #pragma unroll
                for (int mt = 0; mt < 2; mt++)
                    mma_tf32(sacc[mt][nt], af[mt][0], af[mt][1], af[mt][2], af[mt][3],
                             bf[nt][0], bf[nt][1]);
        }

        // add mask in registers
        #pragma unroll
        for (int mt = 0; mt < 2; mt++)
            #pragma unroll
            for (int nt = 0; nt < 4; nt++) {
                sacc[mt][nt][0] += ma[nt].x; sacc[mt][nt][1] += ma[nt].y;
                sacc[mt][nt][2] += ma[nt].x; sacc[mt][nt][3] += ma[nt].y;
            }

        // row max: lane-local (8 cols) -> quad shfl -> half-exchange via smem
        #pragma unroll
        for (int mt = 0; mt < 2; mt++)
            #pragma unroll
            for (int hh = 0; hh < 2; hh++) {
                float mx = fmaxf(sacc[mt][0][2*hh], sacc[mt][0][2*hh+1]);
                #pragma unroll
                for (int nt = 1; nt < 4; nt++)
                    mx = fmaxf(mx, fmaxf(sacc[mt][nt][2*hh], sacc[mt][nt][2*hh+1]));
                mx = fmaxf(mx, __shfl_xor_sync(0xffffffffu, mx, 1));
                mx = fmaxf(mx, __shfl_xor_sync(0xffffffffu, mx, 2));
                if (tg == 0) wmax[wc * 128 + rb + mt * 16 + g + 8 * hh] = mx;
            }
        __syncthreads();   // C

        float mnew[2][2], alpha[2][2], psum[2][2];
        #pragma unroll
        for (int mt = 0; mt < 2; mt++)
            #pragma unroll
            for (int hh = 0; hh < 2; hh++) {
                const int r = rb + mt * 16 + g + 8 * hh;
                const float mo = msh[r];
                const float mn = fmaxf(mo, fmaxf(wmax[r], wmax[128 + r]));
                mnew[mt][hh]  = mn;
                alpha[mt][hh] = __expf(mo - mn);
                float s = 0.0f;
                #pragma unroll
                for (int nt = 0; nt < 4; nt++) {
                    float p0 = __expf(sacc[mt][nt][2*hh]     - mn);
                    float p1 = __expf(sacc[mt][nt][2*hh + 1] - mn);
                    sacc[mt][nt][2*hh]     = __uint_as_float(f2tf32(p0));
                    sacc[mt][nt][2*hh + 1] = __uint_as_float(f2tf32(p1));
                    s += p0 + p1;
                }
                s += __shfl_xor_sync(0xffffffffu, s, 1);
                s += __shfl_xor_sync(0xffffffffu, s, 2);
                psum[mt][hh] = s;
                if (tg == 0) wsum[wc * 128 + r] = s;
            }

        // write P (tf32 bits) for PV ldmatrix loads
        #pragma unroll
        for (int mt = 0; mt < 2; mt++)
            #pragma unroll
            for (int hh = 0; hh < 2; hh++) {
                const int r = rb + mt * 16 + g + 8 * hh;
                #pragma unroll
                for (int nt = 0; nt < 4; nt++) {
                    float2 pv;
                    pv.x = sacc[mt][nt][2*hh];
                    pv.y = sacc[mt][nt][2*hh + 1];
                    *(float2*)(&Ssh[r * PA + wc * 32 + nt * 8 + tg * 2]) = pv;
                }
            }
        __syncthreads();   // D

        // designated lanes update l, m
        if (wc == 0 && tg == 0) {
            #pragma unroll
            for (int mt = 0; mt < 2; mt++)
                #pragma unroll
                for (int hh = 0; hh < 2; hh++) {
                    const int r = rb + mt * 16 + g + 8 * hh;
                    lsh[r] = lsh[r] * alpha[mt][hh] + wsum[r] + wsum[128 + r];
                    msh[r] = mnew[mt][hh];
                }
        }

        // rescale O with locally-computed alpha, then O += P @ V
        #pragma unroll
        for (int mt = 0; mt < 2; mt++)
            #pragma unroll
            for (int nt = 0; nt < 4; nt++) {
                o[mt][nt][0] *= alpha[mt][0]; o[mt][nt][1] *= alpha[mt][0];
                o[mt][nt][2] *= alpha[mt][1]; o[mt][nt][3] *= alpha[mt][1];
            }
        #pragma unroll
        for (int ks = 0; ks < 8; ks++) {
            const int k = ks * 8;
            uint32_t af[2][4];
            #pragma unroll
            for (int mt = 0; mt < 2; mt++)
                ldsm4(af[mt], ssBase + aoffA + (uint32_t)(((rb + mt * 16) * PA + k) * 4));
            uint32_t bf[4][2];
            #pragma unroll
            for (int np = 0; np < 2; np++) {
                uint32_t tt[4];
                ldsm4(tt, vsBase + boffV + (uint32_t)(((wc * 32 + np * 16) * PV + k) * 4));
                bf[np * 2][0] = tt[0]; bf[np * 2][1] = tt[1];
                bf[np * 2 + 1][0] = tt[2]; bf[np * 2 + 1][1] = tt[3];
            }
            #pragma unroll
            for (int nt = 0; nt < 4; nt++)
                #pragma unroll
                for (int mt = 0; mt < 2; mt++)
                    mma_tf32(o[mt][nt], af[mt][0], af[mt][1], af[mt][2], af[mt][3],
                             bf[nt][0], bf[nt][1]);
        }
    }
    __syncthreads();   // final lsh updates visible

    // write context [b, q, h*HD + d] as tf32 bits
    #pragma unroll
    for (int mt = 0; mt < 2; mt++) {
        const int r0 = rb + mt * 16 + g;
        const float inv_lo = 1.0f / lsh[r0];
        const float inv_hi = 1.0f / lsh[r0 + 8];
        #pragma unroll
        for (int nt = 0; nt < 4; nt++) {
            const int d = h * HD + wc * 32 + nt * 8 + tg * 2;
            const int m0 = q0 + r0;
            uint2 u0; u0.x = f2tf32(o[mt][nt][0] * inv_lo); u0.y = f2tf32(o[mt][nt][1] * inv_lo);
            *(uint2*)(&ctx[((size_t)(b * QLEN + m0)) * DIM + d]) = u0;
            uint2 u1; u1.x = f2tf32(o[mt][nt][2] * inv_hi); u1.y = f2tf32(o[mt][nt][3] * inv_hi);
            *(uint2*)(&ctx[((size_t)(b * QLEN + m0 + 8)) * DIM + d]) = u1;
        }
    }
}

// ---------------------------------------------------------------------------
extern "C" void kernel_launch(void* const* d_in, const int* in_sizes, int n_in,
                              void* d_out, int out_size)
{
    const float* x    = (const float*)d_in[0];
    const float* mask = (const float*)d_in[1];
    const float* Wq   = (const float*)d_in[2];
    const float* bq   = (const float*)d_in[3];
    const float* Wk   = (const float*)d_in[4];
    const float* bk   = (const float*)d_in[5];
    const float* Wv   = (const float*)d_in[6];
    const float* bv   = (const float*)d_in[7];
    const float* Wo   = (const float*)d_in[8];
    const float* bo   = (const float*)d_in[9];
    float* out = (float*)d_out;

    uint32_t *Qp, *Kp, *Vp, *Cp, *Xt, *WqkvT, *WoT;
    cudaGetSymbolAddress((void**)&Qp, g_Q);
    cudaGetSymbolAddress((void**)&Kp, g_K);
    cudaGetSymbolAddress((void**)&Vp, g_V);
    cudaGetSymbolAddress((void**)&Cp, g_C);
    cudaGetSymbolAddress((void**)&Xt, g_Xt);
    cudaGetSymbolAddress((void**)&WqkvT, g_WqkvT);
    cudaGetSymbolAddress((void**)&WoT, g_WoT);

    to_tf32<<<MTOT * DIM / 1024, 256>>>(x, Xt);
    transpose_w<<<dim3(32, 32, 4), dim3(32, 8)>>>(Wq, Wk, Wv, Wo, WqkvT, WoT);

    const float qscale = 1.0f / sqrtf((float)HD);

    cudaFuncSetAttribute(gemm_mma<1>, cudaFuncAttributeMaxDynamicSharedMemorySize, GEMM_SMEM);
    cudaFuncSetAttribute(gemm_mma<0>, cudaFuncAttributeMaxDynamicSharedMemorySize, GEMM_SMEM);

    gemm_mma<1><<<dim3(3 * DIM / 128, MTOT / 128), 256, GEMM_SMEM>>>(
        Xt, WqkvT, bq, bk, bv, Qp, Kp, Vp, nullptr, qscale);

    cudaFuncSetAttribute(attn_mma, cudaFuncAttributeMaxDynamicSharedMemorySize, ATTN_SMEM);
    attn_mma<<<dim3(BSZ * NH, QLEN / 128), 256, ATTN_SMEM>>>(Qp, Kp, Vp, mask, Cp);

    gemm_mma<0><<<dim3(DIM / 128, MTOT / 128), 256, GEMM_SMEM>>>(
        Cp, WoT, bo, nullptr, nullptr, nullptr, nullptr, nullptr, out, 1.0f);
}

// round 15
// speedup vs baseline: 4.7297x; 1.0127x over previous
#include <cuda_runtime.h>
#include <cstdint>
#include <math.h>

// Problem dims
#define BSZ   2
#define QLEN  2048
#define DIM   1024
#define NH    16
#define HD    64
#define MTOT  (BSZ*QLEN)   // 4096

// Scratch (device globals). tf32 bit patterns. V is stored [b,h,d,q] (transposed).
__device__ uint32_t g_Q[BSZ*NH*QLEN*HD];
__device__ uint32_t g_K[BSZ*NH*QLEN*HD];
__device__ uint32_t g_V[BSZ*NH*QLEN*HD];
__device__ uint32_t g_C[MTOT*DIM];
__device__ uint32_t g_Xt[MTOT*DIM];
__device__ uint32_t g_WqkvT[3*DIM*DIM];
__device__ uint32_t g_WoT[DIM*DIM];

__device__ __forceinline__ uint32_t smem_u32(const void* p) {
    uint32_t a;
    asm("{ .reg .u64 t; cvta.to.shared.u64 t, %1; cvt.u32.u64 %0, t; }" : "=r"(a) : "l"(p));
    return a;
}
__device__ __forceinline__ void cp16(uint32_t saddr, const void* gaddr) {
    asm volatile("cp.async.cg.shared.global [%0], [%1], 16;" :: "r"(saddr), "l"(gaddr));
}
__device__ __forceinline__ void cp_commit() { asm volatile("cp.async.commit_group;"); }
template<int N>
__device__ __forceinline__ void cp_wait() { asm volatile("cp.async.wait_group %0;" :: "n"(N)); }

__device__ __forceinline__ uint32_t f2tf32(float f) {
    uint32_t u;
    asm("cvt.rna.tf32.f32 %0, %1;" : "=r"(u) : "f"(f));
    return u;
}
__device__ __forceinline__ void mma_tf32(float c[4],
    uint32_t a0, uint32_t a1, uint32_t a2, uint32_t a3, uint32_t b0, uint32_t b1)
{
    asm volatile(
        "mma.sync.aligned.m16n8k8.row.col.f32.tf32.tf32.f32 "
        "{%0,%1,%2,%3}, {%4,%5,%6,%7}, {%8,%9}, {%0,%1,%2,%3};"
        : "+f"(c[0]), "+f"(c[1]), "+f"(c[2]), "+f"(c[3])
        : "r"(a0), "r"(a1), "r"(a2), "r"(a3), "r"(b0), "r"(b1));
}
// ldmatrix x4 of b16 8x8 matrices; on tf32 data each matrix = 8 rows x 4 tf32.
__device__ __forceinline__ void ldsm4(uint32_t r[4], uint32_t addr) {
    asm volatile("ldmatrix.sync.aligned.m8n8.x4.shared.b16 {%0,%1,%2,%3}, [%4];"
        : "=r"(r[0]), "=r"(r[1]), "=r"(r[2]), "=r"(r[3]) : "r"(addr));
}

// ---------------------------------------------------------------------------
// elementwise fp32 -> tf32 bits
// ---------------------------------------------------------------------------
__global__ void to_tf32(const float* __restrict__ in, uint32_t* __restrict__ out)
{
    int idx = (blockIdx.x * 256 + threadIdx.x) * 4;
    float4 v = *(const float4*)(in + idx);
    uint4 u;
    u.x = f2tf32(v.x); u.y = f2tf32(v.y); u.z = f2tf32(v.z); u.w = f2tf32(v.w);
    *(uint4*)(out + idx) = u;
}

// ---------------------------------------------------------------------------
// Batched 32x32 transpose of 4 weight matrices, emits tf32 bits.
// ---------------------------------------------------------------------------
__global__ void transpose_w(const float* __restrict__ w0, const float* __restrict__ w1,
                            const float* __restrict__ w2, const float* __restrict__ w3,
                            uint32_t* __restrict__ qkvT, uint32_t* __restrict__ woT)
{
    __shared__ float tile[32][33];
    const int z = blockIdx.z;
    const float* in = (z == 0) ? w0 : (z == 1) ? w1 : (z == 2) ? w2 : w3;
    uint32_t* out = (z < 3) ? (qkvT + (size_t)z * DIM * DIM) : woT;

    int x = blockIdx.x * 32 + threadIdx.x;
    int y = blockIdx.y * 32 + threadIdx.y;
    #pragma unroll
    for (int i = 0; i < 32; i += 8)
        tile[threadIdx.y + i][threadIdx.x] = in[(size_t)(y + i) * DIM + x];
    __syncthreads();
    int x2 = blockIdx.y * 32 + threadIdx.x;
    int y2 = blockIdx.x * 32 + threadIdx.y;
    #pragma unroll
    for (int i = 0; i < 32; i += 8)
        out[(size_t)(y2 + i) * DIM + x2] = f2tf32(tile[threadIdx.x][threadIdx.y + i]);
}

// ---------------------------------------------------------------------------
// tf32 mma.sync GEMM core, ldmatrix fragment loads. BK=32, dynamic smem.
// MODE 0: fp32 row-major out. MODE 1: QKV fused; V written [b,h,d,q].
// ---------------------------------------------------------------------------
#define BM 128
#define BN 128
#define BK 32
#define PADK 36
#define GEMM_SMEM (2 * 2 * BM * PADK * 4 + BN * 4)

template<int MODE>
__global__ void __launch_bounds__(256) gemm_mma(
    const uint32_t* __restrict__ A, const uint32_t* __restrict__ Wt,
    const float* __restrict__ bias0, const float* __restrict__ bias1,
    const float* __restrict__ bias2,
    uint32_t* __restrict__ q_out, uint32_t* __restrict__ k_out,
    uint32_t* __restrict__ v_out, float* __restrict__ f_out, float qscale)
{
    extern __shared__ unsigned char dynsm[];
    uint32_t* As = (uint32_t*)dynsm;
    uint32_t* Bs = As + 2 * BM * PADK;
    float* s_bias = (float*)(Bs + 2 * BN * PADK);

    const int tid  = threadIdx.x;
    const int wid  = tid >> 5;
    const int lane = tid & 31;
    const int g    = lane >> 2;
    const int tg   = lane & 3;
    const int wr   = wid >> 2;
    const int wc   = wid & 3;
    const int br   = blockIdx.y * BM;
    const int bc   = blockIdx.x * BN;
    const int seg  = (MODE == 1) ? (bc >> 10) : 0;

    if (tid < BN) {
        const float* bp = (MODE == 0) ? bias0
                         : (seg == 0) ? bias0 : (seg == 1) ? bias1 : bias2;
        s_bias[tid] = bp[(MODE == 1 ? (bc & 1023) : bc) + tid];
    }

    const uint32_t aRow = (lane & 7) + ((lane >> 3) & 1) * 8;
    const uint32_t aCol = (lane >> 4) * 4;
    const uint32_t aoffB = (aRow * PADK + aCol) * 4u;
    const uint32_t bRow = (lane & 7) + (lane >> 4) * 8;
    const uint32_t bCol = ((lane >> 3) & 1) * 4;
    const uint32_t boffB = (bRow * PADK + bCol) * 4u;

    uint32_t aAddr[4], bAddr[4];
    const uint32_t* aPtr[4];
    const uint32_t* bPtr[4];
    const uint32_t aBase = smem_u32(As);
    const uint32_t bBase = smem_u32(Bs);
    #pragma unroll
    for (int i = 0; i < 4; i++) {
        int u = i * 256 + tid;
        int row = u >> 3;
        int k4  = (u & 7) * 4;
        aAddr[i] = aBase + (uint32_t)(row * PADK + k4) * 4u;
        bAddr[i] = bBase + (uint32_t)(row * PADK + k4) * 4u;
        aPtr[i]  = A  + (size_t)(br + row) * DIM + k4;
        bPtr[i]  = Wt + (size_t)(bc + row) * DIM + k4;
    }
    const uint32_t stageA = (uint32_t)(BM * PADK) * 4u;
    const uint32_t stageB = (uint32_t)(BN * PADK) * 4u;

    float acc[4][4][4];
    #pragma unroll
    for (int mt = 0; mt < 4; mt++)
        #pragma unroll
        for (int nt = 0; nt < 4; nt++)
            #pragma unroll
            for (int i = 0; i < 4; i++) acc[mt][nt][i] = 0.0f;

    #pragma unroll
    for (int i = 0; i < 4; i++) { cp16(aAddr[i], aPtr[i]); cp16(bAddr[i], bPtr[i]); }
    cp_commit();

    const int KT = DIM / BK;
    for (int kt = 0; kt < KT; kt++) {
        const int buf = kt & 1;
        if (kt + 1 < KT) {
            const int nb = (kt + 1) & 1;
            const int k0 = (kt + 1) * BK;
            #pragma unroll
            for (int i = 0; i < 4; i++) {
                cp16(aAddr[i] + nb * stageA, aPtr[i] + k0);
                cp16(bAddr[i] + nb * stageB, bPtr[i] + k0);
            }
            cp_commit();
            cp_wait<1>();
        } else {
            cp_wait<0>();
        }
        __syncthreads();

        const uint32_t AbB = aBase + buf * stageA + aoffB;
        const uint32_t BbB = bBase + buf * stageB + boffB;
        #pragma unroll
        for (int ks = 0; ks < BK; ks += 8) {
            uint32_t af[4][4];
            #pragma unroll
            for (int mt = 0; mt < 4; mt++)
                ldsm4(af[mt], AbB + (uint32_t)(((wr * 64 + mt * 16) * PADK + ks) * 4));
            uint32_t bf[4][2];
            #pragma unroll
            for (int np = 0; np < 2; np++) {
                uint32_t t[4];
                ldsm4(t, BbB + (uint32_t)(((wc * 32 + np * 16) * PADK + ks) * 4));
                bf[np * 2][0] = t[0]; bf[np * 2][1] = t[1];
                bf[np * 2 + 1][0] = t[2]; bf[np * 2 + 1][1] = t[3];
            }
            #pragma unroll
            for (int mt = 0; mt < 4; mt++)
                #pragma unroll
                for (int nt = 0; nt < 4; nt++)
                    mma_tf32(acc[mt][nt], af[mt][0], af[mt][1], af[mt][2], af[mt][3],
                             bf[nt][0], bf[nt][1]);
        }
        __syncthreads();
    }

    const float scale = (MODE == 1 && seg == 0) ? qscale : 1.0f;
    uint32_t* hs_out = (seg == 0) ? q_out : (seg == 1) ? k_out : v_out;
    #pragma unroll
    for (int mt = 0; mt < 4; mt++) {
        #pragma unroll
        for (int nt = 0; nt < 4; nt++) {
            const int nl = wc * 32 + nt * 8 + tg * 2;
            const float b0 = s_bias[nl], b1 = s_bias[nl + 1];
            #pragma unroll
            for (int half = 0; half < 2; half++) {
                const int m = br + wr * 64 + mt * 16 + g + half * 8;
                float vx = (acc[mt][nt][half * 2 + 0] + b0) * scale;
                float vy = (acc[mt][nt][half * 2 + 1] + b1) * scale;
                if (MODE == 0) {
                    const int n = bc + nl;
                    float2 v; v.x = vx; v.y = vy;
                    *(float2*)(f_out + (size_t)m * DIM + n) = v;
                } else {
                    const int nloc = (bc & 1023) + nl;
                    const int bb = m >> 11, q = m & 2047, h = nloc >> 6, d = nloc & 63;
                    if (seg == 2) {
                        uint32_t* vb = hs_out + ((size_t)(bb * NH + h) * HD) * QLEN;
                        vb[(size_t)d * QLEN + q]       = f2tf32(vx);
                        vb[(size_t)(d + 1) * QLEN + q] = f2tf32(vy);
                    } else {
                        uint2 u; u.x = f2tf32(vx); u.y = f2tf32(vy);
                        *(uint2*)(hs_out + (((size_t)bb * NH + h) * QLEN + q) * HD + d) = u;
                    }
                }
            }
        }
    }
}

// ---------------------------------------------------------------------------
// Tensor-core flash attention; register softmax + staggered K/V prefetch.
// K consumed only by S phase, V only by PV phase -> single-buffered pipeline:
//   prologue: issue K(0)
//   tile t:   issue V(t)  (overlaps S(t) MMAs)
//             wait K(t) -> S(t) -> [Ks free] issue K(t+1) (overlaps softmax+PV)
//             wait V(t) -> PV(t)
// ---------------------------------------------------------------------------
#define PA 68
#define PV 68
#define ATTN_SMEM ((128*PA*2 + 64*PA + 64*PV + 2*128 + 2*256 + 64) * 4)

__global__ void __launch_bounds__(256) attn_mma(
    const uint32_t* __restrict__ Q, const uint32_t* __restrict__ K,
    const uint32_t* __restrict__ V, const float* __restrict__ mask,
    uint32_t* __restrict__ ctx)
{
    extern __shared__ unsigned char smraw[];
    uint32_t* Qs  = (uint32_t*)smraw;                          // 128 x PA
    float*    Ssh = (float*)(smraw + (128*PA)*4);              // 128 x PA (P bits)
    uint32_t* Ks  = (uint32_t*)(smraw + (2*128*PA)*4);         // 64 x PA
    uint32_t* Vs  = (uint32_t*)(smraw + (2*128*PA + 64*PA)*4); // 64 x PV (d-major)
    float*    msh  = (float*)(Vs + 64*PV);                     // 128
    float*    lsh  = msh + 128;                                // 128
    float*    wmax = lsh + 128;                                // 2 x 128
    float*    wsum = wmax + 256;                               // 2 x 128
    float*    madd = wsum + 256;                               // 64

    const int tid  = threadIdx.x;
    const int wid  = tid >> 5;
    const int lane = tid & 31;
    const int g    = lane >> 2;
    const int tg   = lane & 3;
    const int wr   = wid >> 1;
    const int wc   = wid & 1;
    const int rb   = wr * 32;

    const int bh = blockIdx.x;
    const int b  = bh >> 4;
    const int h  = bh & 15;
    const int q0 = blockIdx.y * 128;

    const uint32_t* Qh = Q + (size_t)bh * QLEN * HD;
    const uint32_t* Kh = K + (size_t)bh * QLEN * HD;
    const uint32_t* Vh = V + (size_t)bh * QLEN * HD;   // [d][q]
    const float* mb = mask + (size_t)b * QLEN;

    const uint32_t qsBase = smem_u32(Qs);
    const uint32_t ssBase = smem_u32(Ssh);
    const uint32_t ksBase = smem_u32(Ks);
    const uint32_t vsBase = smem_u32(Vs);

    const uint32_t aRow = (lane & 7) + ((lane >> 3) & 1) * 8;
    const uint32_t aCol = (lane >> 4) * 4;
    const uint32_t aoffA = (aRow * PA + aCol) * 4u;
    const uint32_t bRow = (lane & 7) + (lane >> 4) * 8;
    const uint32_t bCol = ((lane >> 3) & 1) * 4;
    const uint32_t boffK = (bRow * PA + bCol) * 4u;
    const uint32_t boffV = (bRow * PV + bCol) * 4u;

    // per-thread cp.async slots (4 rows x 16-cols-of-4)
    const int cpR  = tid >> 4;            // base row 0..15 (stride 16)
    const int cpC4 = (tid & 15) * 4;      // col 0..60

    // prologue: issue K(0)
    #pragma unroll
    for (int i = 0; i < 4; i++) {
        int r = cpR + i * 16;
        cp16(ksBase + (uint32_t)(r * PA + cpC4) * 4u, Kh + (size_t)r * HD + cpC4);
    }
    cp_commit();

    // stage Q (bit copy)
    #pragma unroll
    for (int i = 0; i < 8; i++) {
        int idx = tid + i * 256;
        int r = idx >> 4, c4 = (idx & 15) * 4;
        *(uint4*)(&Qs[r * PA + c4]) = *(const uint4*)(Qh + (size_t)(q0 + r) * HD + c4);
    }
    if (tid < 128) { msh[tid] = -1e30f; lsh[tid] = 0.0f; }

    float o[2][4][4];
    #pragma unroll
    for (int mt = 0; mt < 2; mt++)
        #pragma unroll
        for (int nt = 0; nt < 4; nt++)
            #pragma unroll
            for (int i = 0; i < 4; i++) o[mt][nt][i] = 0.0f;

    for (int t = 0; t < QLEN / 64; t++) {
        const int kk0 = t * 64;
        __syncthreads();   // A: prev PV done (Vs free); msh/lsh updates visible

        // issue V(t): overlaps S-phase MMAs below
        #pragma unroll
        for (int i = 0; i < 4; i++) {
            int r = cpR + i * 16;
            cp16(vsBase + (uint32_t)(r * PV + cpC4) * 4u, Vh + (size_t)r * QLEN + kk0 + cpC4);
        }
        cp_commit();
        if (tid < 64) madd[tid] = -1e30f * (1.0f - mb[kk0 + tid]);

        cp_wait<1>();      // K(t) done; V(t) may still be in flight
        __syncthreads();   // B

        // mask values for this lane's 8 columns
        float2 ma[4];
        #pragma unroll
        for (int nt = 0; nt < 4; nt++)
            ma[nt] = *(float2*)(&madd[wc * 32 + nt * 8 + tg * 2]);

        // S = Q @ K^T
        float sacc[2][4][4];
        #pragma unroll
        for (int mt = 0; mt < 2; mt++)
            #pragma unroll
            for (int nt = 0; nt < 4; nt++)
                #pragma unroll
                for (int i = 0; i < 4; i++) sacc[mt][nt][i] = 0.0f;

        #pragma unroll
        for (int ks = 0; ks < 8; ks++) {
            const int k = ks * 8;
            uint32_t af[2][4];
            #pragma unroll
            for (int mt = 0; mt < 2; mt++)
                ldsm4(af[mt], qsBase + aoffA + (uint32_t)(((rb + mt * 16) * PA + k) * 4));
            uint32_t bf[4][2];
            #pragma unroll
            for (int np = 0; np < 2; np++) {
                uint32_t tt[4];
                ldsm4(tt, ksBase + boffK + (uint32_t)(((wc * 32 + np * 16) * PA + k) * 4));
                bf[np * 2][0] = tt[0]; bf[np * 2][1] = tt[1];
                bf[np * 2 + 1][0] = tt[2]; bf[np * 2 + 1][1] = tt[3];
            }
            #pragma unroll
            for (int nt = 0; nt < 4; nt++)
                #pragma unroll
                for (int mt = 0; mt < 2; mt++)
                    mma_tf32(sacc[mt][nt], af[mt][0], af[mt][1], af[mt][2], af[mt][3],
                             bf[nt][0], bf[nt][1]);
        }

        // add mask in registers
        #pragma unroll
        for (int mt = 0; mt < 2; mt++)
            #pragma unroll
            for (int nt = 0; nt < 4; nt++) {
                sacc[mt][nt][0] += ma[nt].x; sacc[mt][nt][1] += ma[nt].y;
                sacc[mt][nt][2] += ma[nt].x; sacc[mt][nt][3] += ma[nt].y;
            }

        // row max: lane-local -> quad shfl -> half-exchange via smem
        #pragma unroll
        for (int mt = 0; mt < 2; mt++)
            #pragma unroll
            for (int hh = 0; hh < 2; hh++) {
                float mx = fmaxf(sacc[mt][0][2*hh], sacc[mt][0][2*hh+1]);
                #pragma unroll
                for (int nt = 1; nt < 4; nt++)
                    mx = fmaxf(mx, fmaxf(sacc[mt][nt][2*hh], sacc[mt][nt][2*hh+1]));
                mx = fmaxf(mx, __shfl_xor_sync(0xffffffffu, mx, 1));
                mx = fmaxf(mx, __shfl_xor_sync(0xffffffffu, mx, 2));
                if (tg == 0) wmax[wc * 128 + rb + mt * 16 + g + 8 * hh] = mx;
            }
        __syncthreads();   // C: wmax visible; all S-phase Ks reads done

        // issue K(t+1): overlaps softmax + PV (clamped on last tile)
        {
            const int kknext = (t + 1 < QLEN / 64) ? (kk0 + 64) : kk0;
            #pragma unroll
            for (int i = 0; i < 4; i++) {
                int r = cpR + i * 16;
                cp16(ksBase + (uint32_t)(r * PA + cpC4) * 4u,
                     Kh + (size_t)(kknext + r) * HD + cpC4);
            }
            cp_commit();
        }

        float mnew[2][2], alpha[2][2];
        #pragma unroll
        for (int mt = 0; mt < 2; mt++)
            #pragma unroll
            for (int hh = 0; hh < 2; hh++) {
                const int r = rb + mt * 16 + g + 8 * hh;
                const float mo = msh[r];
                const float mn = fmaxf(mo, fmaxf(wmax[r], wmax[128 + r]));
                mnew[mt][hh]  = mn;
                alpha[mt][hh] = __expf(mo - mn);
                float s = 0.0f;
                #pragma unroll
                for (int nt = 0; nt < 4; nt++) {
                    float p0 = __expf(sacc[mt][nt][2*hh]     - mn);
                    float p1 = __expf(sacc[mt][nt][2*hh + 1] - mn);
                    sacc[mt][nt][2*hh]     = __uint_as_float(f2tf32(p0));
                    sacc[mt][nt][2*hh + 1] = __uint_as_float(f2tf32(p1));
                    s += p0 + p1;
                }
                s += __shfl_xor_sync(0xffffffffu, s, 1);
                s += __shfl_xor_sync(0xffffffffu, s, 2);
                if (tg == 0) wsum[wc * 128 + r] = s;
            }

        // write P (tf32 bits) for PV ldmatrix loads
        #pragma unroll
        for (int mt = 0; mt < 2; mt++)
            #pragma unroll
            for (int hh = 0; hh < 2; hh++) {
                const int r = rb + mt * 16 + g + 8 * hh;
                #pragma unroll
                for (int nt = 0; nt < 4; nt++) {
                    float2 pv;
                    pv.x = sacc[mt][nt][2*hh];
                    pv.y = sacc[mt][nt][2*hh + 1];
                    *(float2*)(&Ssh[r * PA + wc * 32 + nt * 8 + tg * 2]) = pv;
                }
            }

        cp_wait<1>();      // V(t) done; K(t+1) still in flight
        __syncthreads();   // D: P + wsum + Vs visible

        // designated lanes update l, m
        if (wc == 0 && tg == 0) {
            #pragma unroll
            for (int mt = 0; mt < 2; mt++)
                #pragma unroll
                for (int hh = 0; hh < 2; hh++) {
                    const int r = rb + mt * 16 + g + 8 * hh;
                    lsh[r] = lsh[r] * alpha[mt][hh] + wsum[r] + wsum[128 + r];
                    msh[r] = mnew[mt][hh];
                }
        }

        // rescale O with local alpha, then O += P @ V
        #pragma unroll
        for (int mt = 0; mt < 2; mt++)
            #pragma unroll
            for (int nt = 0; nt < 4; nt++) {
                o[mt][nt][0] *= alpha[mt][0]; o[mt][nt][1] *= alpha[mt][0];
                o[mt][nt][2] *= alpha[mt][1]; o[mt][nt][3] *= alpha[mt][1];
            }
        #pragma unroll
        for (int ks = 0; ks < 8; ks++) {
            const int k = ks * 8;
            uint32_t af[2][4];
            #pragma unroll
            for (int mt = 0; mt < 2; mt++)
                ldsm4(af[mt], ssBase + aoffA + (uint32_t)(((rb + mt * 16) * PA + k) * 4));
            uint32_t bf[4][2];
            #pragma unroll
            for (int np = 0; np < 2; np++) {
                uint32_t tt[4];
                ldsm4(tt, vsBase + boffV + (uint32_t)(((wc * 32 + np * 16) * PV + k) * 4));
                bf[np * 2][0] = tt[0]; bf[np * 2][1] = tt[1];
                bf[np * 2 + 1][0] = tt[2]; bf[np * 2 + 1][1] = tt[3];
            }
            #pragma unroll
            for (int nt = 0; nt < 4; nt++)
                #pragma unroll
                for (int mt = 0; mt < 2; mt++)
                    mma_tf32(o[mt][nt], af[mt][0], af[mt][1], af[mt][2], af[mt][3],
                             bf[nt][0], bf[nt][1]);
        }
    }
    __syncthreads();   // final lsh updates visible

    // write context [b, q, h*HD + d] as tf32 bits
    #pragma unroll
    for (int mt = 0; mt < 2; mt++) {
        const int r0 = rb + mt * 16 + g;
        const float inv_lo = 1.0f / lsh[r0];
        const float inv_hi = 1.0f / lsh[r0 + 8];
        #pragma unroll
        for (int nt = 0; nt < 4; nt++) {
            const int d = h * HD + wc * 32 + nt * 8 + tg * 2;
            const int m0 = q0 + r0;
            uint2 u0; u0.x = f2tf32(o[mt][nt][0] * inv_lo); u0.y = f2tf32(o[mt][nt][1] * inv_lo);
            *(uint2*)(&ctx[((size_t)(b * QLEN + m0)) * DIM + d]) = u0;
            uint2 u1; u1.x = f2tf32(o[mt][nt][2] * inv_hi); u1.y = f2tf32(o[mt][nt][3] * inv_hi);
            *(uint2*)(&ctx[((size_t)(b * QLEN + m0 + 8)) * DIM + d]) = u1;
        }
    }
}

// ---------------------------------------------------------------------------
extern "C" void kernel_launch(void* const* d_in, const int* in_sizes, int n_in,
                              void* d_out, int out_size)
{
    const float* x    = (const float*)d_in[0];
    const float* mask = (const float*)d_in[1];
    const float* Wq   = (const float*)d_in[2];
    const float* bq   = (const float*)d_in[3];
    const float* Wk   = (const float*)d_in[4];
    const float* bk   = (const float*)d_in[5];
    const float* Wv   = (const float*)d_in[6];
    const float* bv   = (const float*)d_in[7];
    const float* Wo   = (const float*)d_in[8];
    const float* bo   = (const float*)d_in[9];
    float* out = (float*)d_out;

    uint32_t *Qp, *Kp, *Vp, *Cp, *Xt, *WqkvT, *WoT;
    cudaGetSymbolAddress((void**)&Qp, g_Q);
    cudaGetSymbolAddress((void**)&Kp, g_K);
    cudaGetSymbolAddress((void**)&Vp, g_V);
    cudaGetSymbolAddress((void**)&Cp, g_C);
    cudaGetSymbolAddress((void**)&Xt, g_Xt);
    cudaGetSymbolAddress((void**)&WqkvT, g_WqkvT);
    cudaGetSymbolAddress((void**)&WoT, g_WoT);

    to_tf32<<<MTOT * DIM / 1024, 256>>>(x, Xt);
    transpose_w<<<dim3(32, 32, 4), dim3(32, 8)>>>(Wq, Wk, Wv, Wo, WqkvT, WoT);

    const float qscale = 1.0f / sqrtf((float)HD);

    cudaFuncSetAttribute(gemm_mma<1>, cudaFuncAttributeMaxDynamicSharedMemorySize, GEMM_SMEM);
    cudaFuncSetAttribute(gemm_mma<0>, cudaFuncAttributeMaxDynamicSharedMemorySize, GEMM_SMEM);

    gemm_mma<1><<<dim3(3 * DIM / 128, MTOT / 128), 256, GEMM_SMEM>>>(
        Xt, WqkvT, bq, bk, bv, Qp, Kp, Vp, nullptr, qscale);

    cudaFuncSetAttribute(attn_mma, cudaFuncAttributeMaxDynamicSharedMemorySize, ATTN_SMEM);
    attn_mma<<<dim3(BSZ * NH, QLEN / 128), 256, ATTN_SMEM>>>(Qp, Kp, Vp, mask, Cp);

    gemm_mma<0><<<dim3(DIM / 128, MTOT / 128), 256, GEMM_SMEM>>>(
        Cp, WoT, bo, nullptr, nullptr, nullptr, nullptr, nullptr, out, 1.0f);
}